// round 5
// baseline (speedup 1.0000x reference)
#include <cuda_runtime.h>
#include <cuda_bf16.h>
#include <cstdint>

#define NN 50000
#define EE 800000
#define EPN (EE + NN)          // 850000 edges incl. self loops
#define HC 256
#define NH 4

// ----------------------------- scratch (static device memory) ---------------
__device__ int g_is64;
__device__ int g_src[EE];
__device__ int g_dst[EE];
__device__ __align__(16) float    g_h[NN * HC];      // GEMM output per layer
__device__ __align__(16) float    g_agg[NN * HC];    // scatter accumulator
__device__ __align__(16) float    g_act[NN * HC];    // activations (next layer input)
__device__ __align__(16) float    g_s[NN * NH];      // per-node src logits
__device__ __align__(16) float    g_dv[NN * NH];     // per-node dst logits
__device__ __align__(16) unsigned g_m[NN * NH];      // segment max (order-preserving enc)
__device__ __align__(16) float    g_den[NN * NH];    // softmax denominator
__device__ __align__(16) float    g_e[(size_t)EPN * NH];   // per-edge logits -> weights
__device__ float g_cs[HC], g_css[HC], g_scale[HC], g_shift[HC];
__device__ __align__(16) float g_m1[NN * 32];
__device__ __align__(16) float g_m2[NN * 16];

// ----------------------------- helpers --------------------------------------
__device__ __forceinline__ unsigned enc_f(float f) {
    unsigned u = __float_as_uint(f);
    return (u & 0x80000000u) ? ~u : (u | 0x80000000u);
}
__device__ __forceinline__ float dec_f(unsigned e) {
    return (e & 0x80000000u) ? __uint_as_float(e & 0x7fffffffu) : __uint_as_float(~e);
}
__device__ __forceinline__ void red_add_v4(float* p, float4 v) {
    asm volatile("red.global.add.v4.f32 [%0], {%1,%2,%3,%4};"
                 :: "l"(p), "f"(v.x), "f"(v.y), "f"(v.z), "f"(v.w) : "memory");
}
__device__ __forceinline__ float lrelu(float x, float s) { return x > 0.f ? x : s * x; }

// ----------------------------- index detect/convert -------------------------
__global__ void k_detect(const void* p) {
    const long long* q = (const long long*)p;
    int ok = 1;
    for (int i = 0; i < 8; i++) {
        long long v = q[i];
        if (v < 0 || v >= NN) ok = 0;
    }
    g_is64 = ok;
}
__global__ void k_convert(const void* p) {
    int i = blockIdx.x * blockDim.x + threadIdx.x;
    if (i >= 2 * EE) return;
    long long v = g_is64 ? ((const long long*)p)[i] : (long long)(((const int*)p)[i]);
    int x = (int)v;
    if (i < EE) g_src[i] = x; else g_dst[i - EE] = x;
}

// ----------------------------- SGEMM [NN,256] x [256,256] -------------------
__global__ __launch_bounds__(256) void k_sgemm(const float* __restrict__ A,
                                               const float* __restrict__ B,
                                               float* __restrict__ C) {
    __shared__ float As[16][128];
    __shared__ float Bs[16][64];
    const int tid = threadIdx.x;
    const int row0 = blockIdx.x * 128;
    const int col0 = blockIdx.y * 64;
    const int tm = tid >> 4;        // 0..15 -> rows tm*8..tm*8+7
    const int tn = tid & 15;        // 0..15 -> cols tn*4..tn*4+3
    const int ar = tid >> 2;        // 0..63
    const int ac = (tid & 3) * 4;   // 0,4,8,12
    const int br = tid >> 4;        // 0..15
    const int bc = (tid & 15) * 4;

    float acc[8][4];
#pragma unroll
    for (int i = 0; i < 8; i++)
#pragma unroll
        for (int j = 0; j < 4; j++) acc[i][j] = 0.f;

    for (int k0 = 0; k0 < 256; k0 += 16) {
#pragma unroll
        for (int rr = 0; rr < 2; rr++) {
            int r = ar + rr * 64;
            float4 v = make_float4(0.f, 0.f, 0.f, 0.f);
            if (row0 + r < NN) v = *(const float4*)(A + (size_t)(row0 + r) * 256 + k0 + ac);
            As[ac + 0][r] = v.x; As[ac + 1][r] = v.y; As[ac + 2][r] = v.z; As[ac + 3][r] = v.w;
        }
        {
            float4 v = *(const float4*)(B + (size_t)(k0 + br) * 256 + col0 + bc);
            *(float4*)&Bs[br][bc] = v;
        }
        __syncthreads();
#pragma unroll
        for (int kk = 0; kk < 16; kk++) {
            float a[8], bb[4];
#pragma unroll
            for (int i = 0; i < 8; i++) a[i] = As[kk][tm * 8 + i];
#pragma unroll
            for (int j = 0; j < 4; j++) bb[j] = Bs[kk][tn * 4 + j];
#pragma unroll
            for (int i = 0; i < 8; i++)
#pragma unroll
                for (int j = 0; j < 4; j++) acc[i][j] = fmaf(a[i], bb[j], acc[i][j]);
        }
        __syncthreads();
    }
#pragma unroll
    for (int i = 0; i < 8; i++) {
        int r = row0 + tm * 8 + i;
        if (r < NN)
            *(float4*)(C + (size_t)r * 256 + col0 + tn * 4) =
                make_float4(acc[i][0], acc[i][1], acc[i][2], acc[i][3]);
    }
}

// ----------------------------- per-layer init (zero accumulators) -----------
__global__ void k_init(void) {
    int i = blockIdx.x * blockDim.x + threadIdx.x;
    if (i < NN * HC) g_agg[i] = 0.f;
    if (i < NN * NH) { g_m[i] = 0u; g_den[i] = 0.f; }
    if (i < HC) { g_cs[i] = 0.f; g_css[i] = 0.f; }
}

// ----------------------------- per-node head logits s,d ---------------------
__global__ void k_sd(const float* __restrict__ as_, const float* __restrict__ ad_) {
    int gw = (blockIdx.x * blockDim.x + threadIdx.x) >> 5;
    int lane = threadIdx.x & 31;
    if (gw >= NN) return;
    const float* hr = g_h + (size_t)gw * HC;
    float ps[NH], pd[NH];
#pragma unroll
    for (int h = 0; h < NH; h++) {
        float v0 = hr[h * 64 + lane];
        float v1 = hr[h * 64 + 32 + lane];
        ps[h] = v0 * __ldg(as_ + h * 64 + lane) + v1 * __ldg(as_ + h * 64 + 32 + lane);
        pd[h] = v0 * __ldg(ad_ + h * 64 + lane) + v1 * __ldg(ad_ + h * 64 + 32 + lane);
    }
#pragma unroll
    for (int off = 16; off; off >>= 1)
#pragma unroll
        for (int h = 0; h < NH; h++) {
            ps[h] += __shfl_xor_sync(0xffffffffu, ps[h], off);
            pd[h] += __shfl_xor_sync(0xffffffffu, pd[h], off);
        }
    if (lane < NH) {
        g_s[gw * NH + lane] = ps[lane];
        g_dv[gw * NH + lane] = pd[lane];
    }
}

// ----------------------------- edge pass 1: logits + segment max ------------
__global__ void k_edge1(void) {
    int t = blockIdx.x * blockDim.x + threadIdx.x;
    if (t >= EPN) return;
    int s, d;
    if (t < EE) { s = g_src[t]; d = g_dst[t]; } else { s = t - EE; d = s; }
    float4 sv = *(const float4*)(g_s + s * NH);
    float4 dv = *(const float4*)(g_dv + d * NH);
    float4 e;
    e.x = lrelu(sv.x + dv.x, 0.2f);
    e.y = lrelu(sv.y + dv.y, 0.2f);
    e.z = lrelu(sv.z + dv.z, 0.2f);
    e.w = lrelu(sv.w + dv.w, 0.2f);
    *(float4*)(g_e + (size_t)t * NH) = e;
    unsigned* mp = g_m + d * NH;
    atomicMax(mp + 0, enc_f(e.x));
    atomicMax(mp + 1, enc_f(e.y));
    atomicMax(mp + 2, enc_f(e.z));
    atomicMax(mp + 3, enc_f(e.w));
}

// ----------------------------- edge pass 2: exp + denominator ---------------
__global__ void k_edge2(void) {
    int t = blockIdx.x * blockDim.x + threadIdx.x;
    if (t >= EPN) return;
    int d;
    if (t < EE) d = g_dst[t]; else d = t - EE;
    float4 e = *(const float4*)(g_e + (size_t)t * NH);
    uint4 me = *(const uint4*)(g_m + d * NH);
    float4 w;
    w.x = __expf(e.x - dec_f(me.x));
    w.y = __expf(e.y - dec_f(me.y));
    w.z = __expf(e.z - dec_f(me.z));
    w.w = __expf(e.w - dec_f(me.w));
    *(float4*)(g_e + (size_t)t * NH) = w;
    red_add_v4(g_den + d * NH, w);
}

// ----------------------------- edge pass 3: weighted scatter ----------------
__global__ __launch_bounds__(256) void k_edge3(void) {
    int eid = (blockIdx.x * blockDim.x + threadIdx.x) >> 5;
    int lane = threadIdx.x & 31;
    if (eid >= EPN) return;
    int s, d;
    if (eid < EE) { s = g_src[eid]; d = g_dst[eid]; } else { s = eid - EE; d = s; }
    float4 w = *(const float4*)(g_e + (size_t)eid * NH);
    float4 dn = *(const float4*)(g_den + d * NH);
    float al[4] = { w.x / dn.x, w.y / dn.y, w.z / dn.z, w.w / dn.w };
    const float4* hp = (const float4*)(g_h + (size_t)s * HC);
    float* op = g_agg + (size_t)d * HC;
#pragma unroll
    for (int r = 0; r < 2; r++) {
        int q = lane + r * 32;        // float4 index 0..63
        float a = al[q >> 4];         // head = q*4/64
        float4 v = hp[q];
        v.x *= a; v.y *= a; v.z *= a; v.w *= a;
        red_add_v4(op + q * 4, v);
    }
}

// ----------------------------- column stats (sum, sumsq of v=agg(+mean)+b) --
__global__ void k_colstats(const float* __restrict__ bias, int mode) {
    int c = threadIdx.x;
    float s = 0.f, ss = 0.f;
    float bc = __ldg(bias + c);
    for (int n = blockIdx.x; n < NN; n += gridDim.x) {
        float v;
        if (mode == 0) {
            v = g_agg[(size_t)n * HC + c] + bc;
        } else {
            const float* r = g_agg + (size_t)n * HC;
            v = 0.25f * (r[c] + r[c + 64] + r[c + 128] + r[c + 192]) + bc;
        }
        s += v; ss += v * v;
    }
    atomicAdd(&g_cs[c], s);
    atomicAdd(&g_css[c], ss);
}

__global__ void k_scale(const float* __restrict__ ga, const float* __restrict__ gw,
                        const float* __restrict__ gb) {
    int c = threadIdx.x;
    float inv_n = 1.0f / (float)NN;
    float mu = g_cs[c] * inv_n;
    float ex2 = g_css[c] * inv_n;
    float a = ga[c];
    float var = ex2 - 2.f * a * mu * mu + a * a * mu * mu;
    float inv = rsqrtf(var + 1e-5f);
    float sc = gw[c] * inv;
    g_scale[c] = sc;
    g_shift[c] = gb[c] - sc * a * mu;
}

__global__ void k_norm(const float* __restrict__ bias, int mode) {
    int i = blockIdx.x * blockDim.x + threadIdx.x;
    int D = mode == 0 ? HC : 64;
    if (i >= NN * D) return;
    int c = i % D;
    float v;
    if (mode == 0) {
        v = g_agg[i] + __ldg(bias + c);
    } else {
        int n = i / D;
        const float* r = g_agg + (size_t)n * HC;
        v = 0.25f * (r[c] + r[c + 64] + r[c + 128] + r[c + 192]) + __ldg(bias + c);
    }
    float y = v * g_scale[c] + g_shift[c];
    g_act[i] = lrelu(y, 0.01f);
}

// ----------------------------- MLP ------------------------------------------
template <int DI, int DO, bool RELU>
__global__ void k_fc(const float* __restrict__ in, const float* __restrict__ W,
                     const float* __restrict__ b, float* __restrict__ out) {
    __shared__ float Ws[DI * DO];
    for (int i = threadIdx.x; i < DI * DO; i += blockDim.x) Ws[i] = W[i];
    __syncthreads();
    const int npb = 256 / DO;
    int node = blockIdx.x * npb + threadIdx.x / DO;
    int o = threadIdx.x % DO;
    if (node >= NN) return;
    const float* r = in + (size_t)node * DI;
    float acc = b[o];
#pragma unroll 8
    for (int i = 0; i < DI; i++) acc = fmaf(r[i], Ws[i * DO + o], acc);
    if (RELU) acc = fmaxf(acc, 0.f);
    out[(size_t)node * DO + o] = acc;
}

// ----------------------------- driver ---------------------------------------
extern "C" void kernel_launch(void* const* d_in, const int* in_sizes, int n_in,
                              void* d_out, int out_size) {
    const float* x  = (const float*)d_in[0];
    const void*  ei = d_in[1];
    const float* W[3]  = { (const float*)d_in[2],  (const float*)d_in[9],  (const float*)d_in[16] };
    const float* as_[3] = { (const float*)d_in[3],  (const float*)d_in[10], (const float*)d_in[17] };
    const float* ad_[3] = { (const float*)d_in[4],  (const float*)d_in[11], (const float*)d_in[18] };
    const float* b_[3]  = { (const float*)d_in[5],  (const float*)d_in[12], (const float*)d_in[19] };
    const float* gw_[3] = { (const float*)d_in[6],  (const float*)d_in[13], (const float*)d_in[20] };
    const float* gb_[3] = { (const float*)d_in[7],  (const float*)d_in[14], (const float*)d_in[21] };
    const float* ga_[3] = { (const float*)d_in[8],  (const float*)d_in[15], (const float*)d_in[22] };
    const float* mW0 = (const float*)d_in[23]; const float* mb0 = (const float*)d_in[24];
    const float* mW1 = (const float*)d_in[25]; const float* mb1 = (const float*)d_in[26];
    const float* mW2 = (const float*)d_in[27]; const float* mb2 = (const float*)d_in[28];
    float* out = (float*)d_out;

    float* d_h;   cudaGetSymbolAddress((void**)&d_h,   g_h);
    float* d_act; cudaGetSymbolAddress((void**)&d_act, g_act);
    float* d_m1;  cudaGetSymbolAddress((void**)&d_m1,  g_m1);
    float* d_m2;  cudaGetSymbolAddress((void**)&d_m2,  g_m2);

    k_detect<<<1, 1>>>(ei);
    k_convert<<<(2 * EE + 255) / 256, 256>>>(ei);

    const float* cur = x;
    for (int L = 0; L < 3; L++) {
        k_sgemm<<<dim3((NN + 127) / 128, 4), 256>>>(cur, W[L], d_h);
        k_init<<<(NN * HC + 255) / 256, 256>>>();
        k_sd<<<(NN * 32 + 255) / 256, 256>>>(as_[L], ad_[L]);
        k_edge1<<<(EPN + 255) / 256, 256>>>();
        k_edge2<<<(EPN + 255) / 256, 256>>>();
        k_edge3<<<(EPN * 32 + 255) / 256, 256>>>();
        int mode = (L == 2) ? 1 : 0;
        int D = (L == 2) ? 64 : HC;
        k_colstats<<<256, D>>>(b_[L], mode);
        k_scale<<<1, D>>>(ga_[L], gw_[L], gb_[L]);
        k_norm<<<(NN * D + 255) / 256, 256>>>(b_[L], mode);
        cur = d_act;
    }

    // MLP: dims [64, 32, 16, 2]
    k_fc<64, 32, true ><<<(NN + 7) / 8,   256>>>(d_act, mW0, mb0, d_m1);
    k_fc<32, 16, true ><<<(NN + 15) / 16, 256>>>(d_m1,  mW1, mb1, d_m2);
    k_fc<16, 2,  false><<<(NN + 127) / 128, 256>>>(d_m2, mW2, mb2, out);
}

// round 7
// speedup vs baseline: 1.1748x; 1.1748x over previous
#include <cuda_runtime.h>
#include <cuda_bf16.h>
#include <cstdint>

#define NN 50000
#define EE 800000
#define EPN (EE + NN)
#define HC 256
#define NH 4

// ----------------------------- scratch ---------------------------------------
__device__ int g_is64;
__device__ int g_src[EE];
__device__ int g_dst[EE];
__device__ __align__(16) float    g_h[NN * HC];
__device__ __align__(16) float    g_agg[NN * HC];
__device__ __align__(16) float    g_act[NN * HC];
__device__ __align__(16) __nv_bfloat16 g_Ah[NN * HC];
__device__ __align__(16) __nv_bfloat16 g_Al[NN * HC];
__device__ __align__(16) __nv_bfloat16 g_WTh[3 * 256 * 256];
__device__ __align__(16) __nv_bfloat16 g_WTl[3 * 256 * 256];
__device__ __align__(16) float    g_s[NN * NH];
__device__ __align__(16) float    g_dv[NN * NH];
__device__ __align__(16) unsigned g_m[NN * NH];
__device__ __align__(16) float    g_den[NN * NH];
__device__ __align__(16) float    g_e[(size_t)EPN * NH];
__device__ float g_cs[HC], g_css[HC], g_scale[HC], g_shift[HC];
__device__ __align__(16) float g_m1[NN * 32];
__device__ __align__(16) float g_m2[NN * 16];

// ----------------------------- helpers ---------------------------------------
__device__ __forceinline__ unsigned enc_f(float f) {
    unsigned u = __float_as_uint(f);
    return (u & 0x80000000u) ? ~u : (u | 0x80000000u);
}
__device__ __forceinline__ float dec_f(unsigned e) {
    return (e & 0x80000000u) ? __uint_as_float(e & 0x7fffffffu) : __uint_as_float(~e);
}
__device__ __forceinline__ void red_add_v4(float* p, float4 v) {
    asm volatile("red.global.add.v4.f32 [%0], {%1,%2,%3,%4};"
                 :: "l"(p), "f"(v.x), "f"(v.y), "f"(v.z), "f"(v.w) : "memory");
}
__device__ __forceinline__ float lrelu(float x, float s) { return x > 0.f ? x : s * x; }
__device__ __forceinline__ uint32_t s2u(const void* p) {
    uint32_t a;
    asm("{ .reg .u64 t; cvta.to.shared.u64 t, %1; cvt.u32.u64 %0, t; }" : "=r"(a) : "l"(p));
    return a;
}
__device__ __forceinline__ void ldsm4(uint32_t* r, uint32_t addr) {
    asm volatile("ldmatrix.sync.aligned.m8n8.x4.shared.b16 {%0,%1,%2,%3}, [%4];"
                 : "=r"(r[0]), "=r"(r[1]), "=r"(r[2]), "=r"(r[3]) : "r"(addr));
}
__device__ __forceinline__ void mma16816(float* d, const uint32_t* a, const uint32_t* b) {
    asm volatile("mma.sync.aligned.m16n8k16.row.col.f32.bf16.bf16.f32 "
                 "{%0,%1,%2,%3},{%4,%5,%6,%7},{%8,%9},{%0,%1,%2,%3};"
                 : "+f"(d[0]), "+f"(d[1]), "+f"(d[2]), "+f"(d[3])
                 : "r"(a[0]), "r"(a[1]), "r"(a[2]), "r"(a[3]), "r"(b[0]), "r"(b[1]));
}

// ----------------------------- index detect/convert --------------------------
__global__ void k_detect(const void* p) {
    const long long* q = (const long long*)p;
    int ok = 1;
    for (int i = 0; i < 8; i++) {
        long long v = q[i];
        if (v < 0 || v >= NN) ok = 0;
    }
    g_is64 = ok;
}
__global__ void k_convert(const void* p) {
    int i = blockIdx.x * blockDim.x + threadIdx.x;
    if (i >= 2 * EE) return;
    long long v = g_is64 ? ((const long long*)p)[i] : (long long)(((const int*)p)[i]);
    int x = (int)v;
    if (i < EE) g_src[i] = x; else g_dst[i - EE] = x;
}

// ----------------------------- input / weight split --------------------------
__global__ void k_convx(const float* __restrict__ x) {
    int i = blockIdx.x * blockDim.x + threadIdx.x;
    if (i >= NN * HC) return;
    float v = x[i];
    __nv_bfloat16 h = __float2bfloat16(v);
    g_Ah[i] = h;
    g_Al[i] = __float2bfloat16(v - __bfloat162float(h));
}
__global__ void k_prep_w(const float* __restrict__ W, int L) {
    int n = blockIdx.x, k = threadIdx.x;            // 256 x 256
    float w = W[k * 256 + n];
    size_t o = (size_t)L * 65536 + n * 256 + k;     // [n, k] = W^T
    __nv_bfloat16 h = __float2bfloat16(w);
    g_WTh[o] = h;
    g_WTl[o] = __float2bfloat16(w - __bfloat162float(h));
}

// ----------------------------- mma.sync GEMM ---------------------------------
// C[50000,256] = A * W ; A split bf16 hi/lo [NN,256], B = W^T split [256,256].
// CTA: 128(M) x 64(N), K chunks of 32. 8 warps = 4M x 2N, warp tile 32x32.
#define KCH 32
#define ROWB 80                       // padded smem row stride (bytes) per 32 bf16
#define OA_H 0
#define OA_L (OA_H + 128 * ROWB)      // 10240
#define OB_H (OA_L + 128 * ROWB)      // 20480
#define OB_L (OB_H + 64 * ROWB)       // 25600
#define SMEM_SZ (OB_L + 64 * ROWB)    // 30720

__global__ __launch_bounds__(256) void k_gemm_mma(
    const __nv_bfloat16* __restrict__ Ah, const __nv_bfloat16* __restrict__ Al,
    const __nv_bfloat16* __restrict__ Bh, const __nv_bfloat16* __restrict__ Bl,
    float* __restrict__ C) {
    __shared__ __align__(16) char smem[SMEM_SZ];
    const uint32_t sb = s2u(smem);
    const int tid = threadIdx.x;
    const int wid = tid >> 5, lane = tid & 31;
    const int m0 = blockIdx.x * 128;
    const int n0 = blockIdx.y * 64;
    const int wm = (wid >> 1) * 32;
    const int wn = (wid & 1) * 32;

    float acc[2][4][4];
#pragma unroll
    for (int i = 0; i < 2; i++)
#pragma unroll
        for (int j = 0; j < 4; j++)
#pragma unroll
            for (int q = 0; q < 4; q++) acc[i][j][q] = 0.f;

    // ldmatrix lane addressing (constant across chunks except k-unit)
    const int lq = lane >> 3, lr = lane & 7;

    for (int ch = 0; ch < 8; ch++) {
        const int k0 = ch * KCH;
        __syncthreads();
        // A: 128 rows x 32 cols (hi+lo): 512 16B segs each
#pragma unroll
        for (int s = tid; s < 512; s += 256) {
            int r = s >> 2, kq = s & 3;
            int gr = m0 + r;
            uint4 vh = make_uint4(0, 0, 0, 0), vl = vh;
            if (gr < NN) {
                vh = *(const uint4*)(Ah + (size_t)gr * HC + k0 + kq * 8);
                vl = *(const uint4*)(Al + (size_t)gr * HC + k0 + kq * 8);
            }
            *(uint4*)(smem + OA_H + r * ROWB + kq * 16) = vh;
            *(uint4*)(smem + OA_L + r * ROWB + kq * 16) = vl;
        }
        // B: 64 n-rows x 32 k-cols (hi+lo): 256 segs each
        {
            int r = tid >> 2, kq = tid & 3;
            uint4 vh = *(const uint4*)(Bh + (size_t)(n0 + r) * HC + k0 + kq * 8);
            uint4 vl = *(const uint4*)(Bl + (size_t)(n0 + r) * HC + k0 + kq * 8);
            *(uint4*)(smem + OB_H + r * ROWB + kq * 16) = vh;
            *(uint4*)(smem + OB_L + r * ROWB + kq * 16) = vl;
        }
        __syncthreads();

#pragma unroll
        for (int ks = 0; ks < 2; ks++) {
            uint32_t ah[2][4], al[2][4], bh[2][4], bl[2][4];
            // A fragments: mt = 0,1 ; quadrants: (q&1)->m+8, (q>>1)->k+8
#pragma unroll
            for (int mt = 0; mt < 2; mt++) {
                int row = wm + mt * 16 + (lq & 1) * 8 + lr;
                int u = ks * 2 + (lq >> 1);
                ldsm4(ah[mt], sb + OA_H + row * ROWB + u * 16);
                ldsm4(al[mt], sb + OA_L + row * ROWB + u * 16);
            }
            // B fragments: p = 0,1 covers nt pair {2p, 2p+1}
            // matrix j: n = wn + p*16 + (j>>1)*8 + lr ; u = ks*2 + (j&1)
#pragma unroll
            for (int p = 0; p < 2; p++) {
                int n = wn + p * 16 + (lq >> 1) * 8 + lr;
                int u = ks * 2 + (lq & 1);
                ldsm4(bh[p], sb + OB_H + n * ROWB + u * 16);
                ldsm4(bl[p], sb + OB_L + n * ROWB + u * 16);
            }
#pragma unroll
            for (int mt = 0; mt < 2; mt++)
#pragma unroll
                for (int nt = 0; nt < 4; nt++) {
                    const uint32_t* ph = &bh[nt >> 1][(nt & 1) * 2];
                    const uint32_t* pl = &bl[nt >> 1][(nt & 1) * 2];
                    mma16816(acc[mt][nt], ah[mt], ph);   // Ah*Bh
                    mma16816(acc[mt][nt], ah[mt], pl);   // Ah*Bl
                    mma16816(acc[mt][nt], al[mt], ph);   // Al*Bh
                }
        }
    }

    // epilogue: d0,d1 -> (row=g, col=tg*2), d2,d3 -> (row=g+8)
    const int g = lane >> 2, tg = lane & 3;
#pragma unroll
    for (int mt = 0; mt < 2; mt++) {
        int r0 = m0 + wm + mt * 16 + g;
#pragma unroll
        for (int nt = 0; nt < 4; nt++) {
            int c = n0 + wn + nt * 8 + tg * 2;
            if (r0 < NN)
                *(float2*)(C + (size_t)r0 * HC + c) = make_float2(acc[mt][nt][0], acc[mt][nt][1]);
            if (r0 + 8 < NN)
                *(float2*)(C + (size_t)(r0 + 8) * HC + c) = make_float2(acc[mt][nt][2], acc[mt][nt][3]);
        }
    }
}

// ----------------------------- per-layer init --------------------------------
__global__ void k_init(void) {
    int i = blockIdx.x * blockDim.x + threadIdx.x;
    if (i < NN * HC) g_agg[i] = 0.f;
    if (i < NN * NH) { g_m[i] = 0u; g_den[i] = 0.f; }
    if (i < HC) { g_cs[i] = 0.f; g_css[i] = 0.f; }
}

// ----------------------------- per-node head logits --------------------------
__global__ void k_sd(const float* __restrict__ as_, const float* __restrict__ ad_) {
    int gw = (blockIdx.x * blockDim.x + threadIdx.x) >> 5;
    int lane = threadIdx.x & 31;
    if (gw >= NN) return;
    const float* hr = g_h + (size_t)gw * HC;
    float ps[NH], pd[NH];
#pragma unroll
    for (int h = 0; h < NH; h++) {
        float v0 = hr[h * 64 + lane];
        float v1 = hr[h * 64 + 32 + lane];
        ps[h] = v0 * __ldg(as_ + h * 64 + lane) + v1 * __ldg(as_ + h * 64 + 32 + lane);
        pd[h] = v0 * __ldg(ad_ + h * 64 + lane) + v1 * __ldg(ad_ + h * 64 + 32 + lane);
    }
#pragma unroll
    for (int off = 16; off; off >>= 1)
#pragma unroll
        for (int h = 0; h < NH; h++) {
            ps[h] += __shfl_xor_sync(0xffffffffu, ps[h], off);
            pd[h] += __shfl_xor_sync(0xffffffffu, pd[h], off);
        }
    if (lane < NH) {
        g_s[gw * NH + lane] = ps[lane];
        g_dv[gw * NH + lane] = pd[lane];
    }
}

// ----------------------------- edge passes -----------------------------------
__global__ void k_edge1(void) {
    int t = blockIdx.x * blockDim.x + threadIdx.x;
    if (t >= EPN) return;
    int s, d;
    if (t < EE) { s = g_src[t]; d = g_dst[t]; } else { s = t - EE; d = s; }
    float4 sv = *(const float4*)(g_s + s * NH);
    float4 dv = *(const float4*)(g_dv + d * NH);
    float4 e;
    e.x = lrelu(sv.x + dv.x, 0.2f);
    e.y = lrelu(sv.y + dv.y, 0.2f);
    e.z = lrelu(sv.z + dv.z, 0.2f);
    e.w = lrelu(sv.w + dv.w, 0.2f);
    *(float4*)(g_e + (size_t)t * NH) = e;
    unsigned* mp = g_m + d * NH;
    atomicMax(mp + 0, enc_f(e.x));
    atomicMax(mp + 1, enc_f(e.y));
    atomicMax(mp + 2, enc_f(e.z));
    atomicMax(mp + 3, enc_f(e.w));
}
__global__ void k_edge2(void) {
    int t = blockIdx.x * blockDim.x + threadIdx.x;
    if (t >= EPN) return;
    int d;
    if (t < EE) d = g_dst[t]; else d = t - EE;
    float4 e = *(const float4*)(g_e + (size_t)t * NH);
    uint4 me = *(const uint4*)(g_m + d * NH);
    float4 w;
    w.x = __expf(e.x - dec_f(me.x));
    w.y = __expf(e.y - dec_f(me.y));
    w.z = __expf(e.z - dec_f(me.z));
    w.w = __expf(e.w - dec_f(me.w));
    *(float4*)(g_e + (size_t)t * NH) = w;
    red_add_v4(g_den + d * NH, w);
}
__global__ __launch_bounds__(256) void k_edge3(void) {
    int eid = (blockIdx.x * blockDim.x + threadIdx.x) >> 5;
    int lane = threadIdx.x & 31;
    if (eid >= EPN) return;
    int s, d;
    if (eid < EE) { s = g_src[eid]; d = g_dst[eid]; } else { s = eid - EE; d = s; }
    float4 w = *(const float4*)(g_e + (size_t)eid * NH);
    float4 dn = *(const float4*)(g_den + d * NH);
    float al[4] = { w.x / dn.x, w.y / dn.y, w.z / dn.z, w.w / dn.w };
    const float4* hp = (const float4*)(g_h + (size_t)s * HC);
    float* op = g_agg + (size_t)d * HC;
#pragma unroll
    for (int r = 0; r < 2; r++) {
        int q = lane + r * 32;
        float a = al[q >> 4];
        float4 v = hp[q];
        v.x *= a; v.y *= a; v.z *= a; v.w *= a;
        red_add_v4(op + q * 4, v);
    }
}

// ----------------------------- graph norm ------------------------------------
__global__ void k_colstats(const float* __restrict__ bias, int mode) {
    int c = threadIdx.x;
    float s = 0.f, ss = 0.f;
    float bc = __ldg(bias + c);
    for (int n = blockIdx.x; n < NN; n += gridDim.x) {
        float v;
        if (mode == 0) {
            v = g_agg[(size_t)n * HC + c] + bc;
        } else {
            const float* r = g_agg + (size_t)n * HC;
            v = 0.25f * (r[c] + r[c + 64] + r[c + 128] + r[c + 192]) + bc;
        }
        s += v; ss += v * v;
    }
    atomicAdd(&g_cs[c], s);
    atomicAdd(&g_css[c], ss);
}
__global__ void k_scale(const float* __restrict__ ga, const float* __restrict__ gw,
                        const float* __restrict__ gb) {
    int c = threadIdx.x;
    float inv_n = 1.0f / (float)NN;
    float mu = g_cs[c] * inv_n;
    float ex2 = g_css[c] * inv_n;
    float a = ga[c];
    float var = ex2 - 2.f * a * mu * mu + a * a * mu * mu;
    float inv = rsqrtf(var + 1e-5f);
    float sc = gw[c] * inv;
    g_scale[c] = sc;
    g_shift[c] = gb[c] - sc * a * mu;
}
// mode 0: emit next-layer GEMM operand as bf16 hi/lo. mode 1: fp32 for MLP.
__global__ void k_norm(const float* __restrict__ bias, int mode) {
    int i = blockIdx.x * blockDim.x + threadIdx.x;
    int D = mode == 0 ? HC : 64;
    if (i >= NN * D) return;
    int c = i % D;
    float v;
    if (mode == 0) {
        v = g_agg[i] + __ldg(bias + c);
    } else {
        int n = i / D;
        const float* r = g_agg + (size_t)n * HC;
        v = 0.25f * (r[c] + r[c + 64] + r[c + 128] + r[c + 192]) + __ldg(bias + c);
    }
    float y = lrelu(v * g_scale[c] + g_shift[c], 0.01f);
    if (mode == 0) {
        __nv_bfloat16 h = __float2bfloat16(y);
        g_Ah[i] = h;
        g_Al[i] = __float2bfloat16(y - __bfloat162float(h));
    } else {
        g_act[i] = y;
    }
}

// ----------------------------- MLP -------------------------------------------
template <int DI, int DO, bool RELU>
__global__ void k_fc(const float* __restrict__ in, const float* __restrict__ W,
                     const float* __restrict__ b, float* __restrict__ out) {
    __shared__ float Ws[DI * DO];
    for (int i = threadIdx.x; i < DI * DO; i += blockDim.x) Ws[i] = W[i];
    __syncthreads();
    const int npb = 256 / DO;
    int node = blockIdx.x * npb + threadIdx.x / DO;
    int o = threadIdx.x % DO;
    if (node >= NN) return;
    const float* r = in + (size_t)node * DI;
    float acc = b[o];
#pragma unroll 8
    for (int i = 0; i < DI; i++) acc = fmaf(r[i], Ws[i * DO + o], acc);
    if (RELU) acc = fmaxf(acc, 0.f);
    out[(size_t)node * DO + o] = acc;
}

// ----------------------------- driver ----------------------------------------
extern "C" void kernel_launch(void* const* d_in, const int* in_sizes, int n_in,
                              void* d_out, int out_size) {
    const float* x  = (const float*)d_in[0];
    const void*  ei = d_in[1];
    const float* W[3]   = { (const float*)d_in[2],  (const float*)d_in[9],  (const float*)d_in[16] };
    const float* as_[3] = { (const float*)d_in[3],  (const float*)d_in[10], (const float*)d_in[17] };
    const float* ad_[3] = { (const float*)d_in[4],  (const float*)d_in[11], (const float*)d_in[18] };
    const float* b_[3]  = { (const float*)d_in[5],  (const float*)d_in[12], (const float*)d_in[19] };
    const float* gw_[3] = { (const float*)d_in[6],  (const float*)d_in[13], (const float*)d_in[20] };
    const float* gb_[3] = { (const float*)d_in[7],  (const float*)d_in[14], (const float*)d_in[21] };
    const float* ga_[3] = { (const float*)d_in[8],  (const float*)d_in[15], (const float*)d_in[22] };
    const float* mW0 = (const float*)d_in[23]; const float* mb0 = (const float*)d_in[24];
    const float* mW1 = (const float*)d_in[25]; const float* mb1 = (const float*)d_in[26];
    const float* mW2 = (const float*)d_in[27]; const float* mb2 = (const float*)d_in[28];
    float* out = (float*)d_out;

    float* d_h;   cudaGetSymbolAddress((void**)&d_h,   g_h);
    float* d_act; cudaGetSymbolAddress((void**)&d_act, g_act);
    float* d_m1;  cudaGetSymbolAddress((void**)&d_m1,  g_m1);
    float* d_m2;  cudaGetSymbolAddress((void**)&d_m2,  g_m2);
    __nv_bfloat16* d_Ah;  cudaGetSymbolAddress((void**)&d_Ah,  g_Ah);
    __nv_bfloat16* d_Al;  cudaGetSymbolAddress((void**)&d_Al,  g_Al);
    __nv_bfloat16* d_WTh; cudaGetSymbolAddress((void**)&d_WTh, g_WTh);
    __nv_bfloat16* d_WTl; cudaGetSymbolAddress((void**)&d_WTl, g_WTl);

    k_detect<<<1, 1>>>(ei);
    k_convert<<<(2 * EE + 255) / 256, 256>>>(ei);
    for (int L = 0; L < 3; L++) k_prep_w<<<256, 256>>>(W[L], L);
    k_convx<<<(NN * HC + 255) / 256, 256>>>(x);

    const int GB = (NN + 127) / 128;   // 391
    for (int L = 0; L < 3; L++) {
        k_gemm_mma<<<dim3(GB, 4), 256>>>(d_Ah, d_Al,
                                         d_WTh + (size_t)L * 65536, d_WTl + (size_t)L * 65536,
                                         d_h);
        k_init<<<(NN * HC + 255) / 256, 256>>>();
        k_sd<<<(NN * 32 + 255) / 256, 256>>>(as_[L], ad_[L]);
        k_edge1<<<(EPN + 255) / 256, 256>>>();
        k_edge2<<<(EPN + 255) / 256, 256>>>();
        k_edge3<<<(EPN * 32 + 255) / 256, 256>>>();
        int mode = (L == 2) ? 1 : 0;
        int D = (L == 2) ? 64 : HC;
        k_colstats<<<256, D>>>(b_[L], mode);
        k_scale<<<1, D>>>(ga_[L], gw_[L], gb_[L]);
        k_norm<<<(NN * D + 255) / 256, 256>>>(b_[L], mode);
    }

    // MLP: dims [64, 32, 16, 2]
    k_fc<64, 32, true ><<<(NN + 7) / 8,   256>>>(d_act, mW0, mb0, d_m1);
    k_fc<32, 16, true ><<<(NN + 15) / 16, 256>>>(d_m1,  mW1, mb1, d_m2);
    k_fc<16, 2,  false><<<(NN + 127) / 128, 256>>>(d_m2, mW2, mb2, out);
}

// round 11
// speedup vs baseline: 1.6006x; 1.3625x over previous
#include <cuda_runtime.h>
#include <cuda_bf16.h>
#include <cstdint>

#define NN 50000
#define EE 800000
#define EPN (EE + NN)
#define HC 256
#define NH 4
#define NSCB 196                        // ceil(NN/256) scan blocks

// ----------------------------- scratch ---------------------------------------
__device__ int g_is64;
__device__ int g_src[EE];
__device__ int g_dst[EE];
__device__ int g_cnt[NN];
__device__ int g_loc[NN];
__device__ int g_bsum[256];
__device__ int g_bpre[256];
__device__ int g_segoff[NN + 1];
__device__ int g_fill[NN];
__device__ int g_ssrc[EPN];
__device__ __align__(16) float    g_h[NN * HC];
__device__ __align__(16) float    g_agg[NN * HC];
__device__ __align__(16) float    g_act[NN * HC];
__device__ __align__(16) __nv_bfloat16 g_Ah[NN * HC];
__device__ __align__(16) __nv_bfloat16 g_Al[NN * HC];
__device__ __align__(16) __nv_bfloat16 g_WTh[3 * 256 * 256];
__device__ __align__(16) __nv_bfloat16 g_WTl[3 * 256 * 256];
__device__ __align__(16) float    g_s[NN * NH];
__device__ __align__(16) float    g_dv[NN * NH];
__device__ float g_cs[HC], g_css[HC], g_scale[HC], g_shift[HC];
__device__ __align__(16) float g_m1[NN * 32];
__device__ __align__(16) float g_m2[NN * 16];

// ----------------------------- helpers ---------------------------------------
__device__ __forceinline__ float lrelu(float x, float s) { return x > 0.f ? x : s * x; }
__device__ __forceinline__ uint32_t s2u(const void* p) {
    uint32_t a;
    asm("{ .reg .u64 t; cvta.to.shared.u64 t, %1; cvt.u32.u64 %0, t; }" : "=r"(a) : "l"(p));
    return a;
}
__device__ __forceinline__ void ldsm4(uint32_t* r, uint32_t addr) {
    asm volatile("ldmatrix.sync.aligned.m8n8.x4.shared.b16 {%0,%1,%2,%3}, [%4];"
                 : "=r"(r[0]), "=r"(r[1]), "=r"(r[2]), "=r"(r[3]) : "r"(addr));
}
__device__ __forceinline__ void mma16816(float* d, const uint32_t* a, const uint32_t* b) {
    asm volatile("mma.sync.aligned.m16n8k16.row.col.f32.bf16.bf16.f32 "
                 "{%0,%1,%2,%3},{%4,%5,%6,%7},{%8,%9},{%0,%1,%2,%3};"
                 : "+f"(d[0]), "+f"(d[1]), "+f"(d[2]), "+f"(d[3])
                 : "r"(a[0]), "r"(a[1]), "r"(a[2]), "r"(a[3]), "r"(b[0]), "r"(b[1]));
}

// ----------------------------- index detect/convert --------------------------
__global__ void k_detect(const void* p) {
    const long long* q = (const long long*)p;
    int ok = 1;
    for (int i = 0; i < 8; i++) {
        long long v = q[i];
        if (v < 0 || v >= NN) ok = 0;
    }
    g_is64 = ok;
}
__global__ void k_convert(const void* p) {
    int i = blockIdx.x * blockDim.x + threadIdx.x;
    if (i >= 2 * EE) return;
    long long v = g_is64 ? ((const long long*)p)[i] : (long long)(((const int*)p)[i]);
    int x = (int)v;
    if (i < EE) g_src[i] = x; else g_dst[i - EE] = x;
}

// ----------------------------- dst counting sort ------------------------------
__global__ void k_zcnt(void) {
    int i = blockIdx.x * blockDim.x + threadIdx.x;
    if (i < NN) g_cnt[i] = 0;
}
__global__ void k_hist(void) {
    int t = blockIdx.x * blockDim.x + threadIdx.x;
    if (t >= EPN) return;
    int d = (t < EE) ? g_dst[t] : t - EE;
    atomicAdd(&g_cnt[d], 1);
}
__global__ void k_scan1(void) {
    __shared__ int sh[256];
    int t = threadIdx.x, b = blockIdx.x;
    int i = b * 256 + t;
    int v = (i < NN) ? g_cnt[i] : 0;
    sh[t] = v;
    __syncthreads();
#pragma unroll
    for (int off = 1; off < 256; off <<= 1) {
        int add = (t >= off) ? sh[t - off] : 0;
        __syncthreads();
        sh[t] += add;
        __syncthreads();
    }
    if (i < NN) g_loc[i] = sh[t] - v;
    if (t == 255) g_bsum[b] = sh[t];
}
__global__ void k_scan2(void) {
    __shared__ int sh[256];
    int t = threadIdx.x;
    int v = (t < NSCB) ? g_bsum[t] : 0;
    sh[t] = v;
    __syncthreads();
#pragma unroll
    for (int off = 1; off < 256; off <<= 1) {
        int add = (t >= off) ? sh[t - off] : 0;
        __syncthreads();
        sh[t] += add;
        __syncthreads();
    }
    g_bpre[t] = sh[t] - v;
}
__global__ void k_scan3(void) {
    int i = blockIdx.x * blockDim.x + threadIdx.x;
    if (i >= NN) return;
    int off = g_loc[i] + g_bpre[i >> 8];
    g_segoff[i] = off;
    g_fill[i] = off;
    if (i == 0) g_segoff[NN] = EPN;
}
__global__ void k_scatter(void) {
    int t = blockIdx.x * blockDim.x + threadIdx.x;
    if (t >= EPN) return;
    int s, d;
    if (t < EE) { s = g_src[t]; d = g_dst[t]; } else { s = t - EE; d = s; }
    int pos = atomicAdd(&g_fill[d], 1);
    g_ssrc[pos] = s;
}

// ----------------------------- input / weight split --------------------------
__global__ void k_convx(const float* __restrict__ x) {
    int i = blockIdx.x * blockDim.x + threadIdx.x;
    if (i >= NN * HC) return;
    float v = x[i];
    __nv_bfloat16 h = __float2bfloat16(v);
    g_Ah[i] = h;
    g_Al[i] = __float2bfloat16(v - __bfloat162float(h));
}
__global__ void k_prep_w(const float* __restrict__ W, int L) {
    int n = blockIdx.x, k = threadIdx.x;
    float w = W[k * 256 + n];
    size_t o = (size_t)L * 65536 + n * 256 + k;
    __nv_bfloat16 h = __float2bfloat16(w);
    g_WTh[o] = h;
    g_WTl[o] = __float2bfloat16(w - __bfloat162float(h));
}

// ----------------------------- mma.sync GEMM ---------------------------------
#define KCH 32
#define ROWB 80
#define OA_H 0
#define OA_L (OA_H + 128 * ROWB)
#define OB_H (OA_L + 128 * ROWB)
#define OB_L (OB_H + 64 * ROWB)
#define SMEM_SZ (OB_L + 64 * ROWB)

__global__ __launch_bounds__(256) void k_gemm_mma(
    const __nv_bfloat16* __restrict__ Ah, const __nv_bfloat16* __restrict__ Al,
    const __nv_bfloat16* __restrict__ Bh, const __nv_bfloat16* __restrict__ Bl,
    float* __restrict__ C) {
    __shared__ __align__(16) char smem[SMEM_SZ];
    const uint32_t sb = s2u(smem);
    const int tid = threadIdx.x;
    const int wid = tid >> 5, lane = tid & 31;
    const int m0 = blockIdx.x * 128;
    const int n0 = blockIdx.y * 64;
    const int wm = (wid >> 1) * 32;
    const int wn = (wid & 1) * 32;

    float acc[2][4][4];
#pragma unroll
    for (int i = 0; i < 2; i++)
#pragma unroll
        for (int j = 0; j < 4; j++)
#pragma unroll
            for (int q = 0; q < 4; q++) acc[i][j][q] = 0.f;

    const int lq = lane >> 3, lr = lane & 7;

    for (int ch = 0; ch < 8; ch++) {
        const int k0 = ch * KCH;
        __syncthreads();
#pragma unroll
        for (int s = tid; s < 512; s += 256) {
            int r = s >> 2, kq = s & 3;
            int gr = m0 + r;
            uint4 vh = make_uint4(0, 0, 0, 0), vl = vh;
            if (gr < NN) {
                vh = *(const uint4*)(Ah + (size_t)gr * HC + k0 + kq * 8);
                vl = *(const uint4*)(Al + (size_t)gr * HC + k0 + kq * 8);
            }
            *(uint4*)(smem + OA_H + r * ROWB + kq * 16) = vh;
            *(uint4*)(smem + OA_L + r * ROWB + kq * 16) = vl;
        }
        {
            int r = tid >> 2, kq = tid & 3;
            uint4 vh = *(const uint4*)(Bh + (size_t)(n0 + r) * HC + k0 + kq * 8);
            uint4 vl = *(const uint4*)(Bl + (size_t)(n0 + r) * HC + k0 + kq * 8);
            *(uint4*)(smem + OB_H + r * ROWB + kq * 16) = vh;
            *(uint4*)(smem + OB_L + r * ROWB + kq * 16) = vl;
        }
        __syncthreads();

#pragma unroll
        for (int ks = 0; ks < 2; ks++) {
            uint32_t ah[2][4], al[2][4], bh[2][4], bl[2][4];
#pragma unroll
            for (int mt = 0; mt < 2; mt++) {
                int row = wm + mt * 16 + (lq & 1) * 8 + lr;
                int u = ks * 2 + (lq >> 1);
                ldsm4(ah[mt], sb + OA_H + row * ROWB + u * 16);
                ldsm4(al[mt], sb + OA_L + row * ROWB + u * 16);
            }
#pragma unroll
            for (int p = 0; p < 2; p++) {
                int n = wn + p * 16 + (lq >> 1) * 8 + lr;
                int u = ks * 2 + (lq & 1);
                ldsm4(bh[p], sb + OB_H + n * ROWB + u * 16);
                ldsm4(bl[p], sb + OB_L + n * ROWB + u * 16);
            }
#pragma unroll
            for (int mt = 0; mt < 2; mt++)
#pragma unroll
                for (int nt = 0; nt < 4; nt++) {
                    const uint32_t* ph = &bh[nt >> 1][(nt & 1) * 2];
                    const uint32_t* pl = &bl[nt >> 1][(nt & 1) * 2];
                    mma16816(acc[mt][nt], ah[mt], ph);
                    mma16816(acc[mt][nt], ah[mt], pl);
                    mma16816(acc[mt][nt], al[mt], ph);
                }
        }
    }

    const int g = lane >> 2, tg = lane & 3;
#pragma unroll
    for (int mt = 0; mt < 2; mt++) {
        int r0 = m0 + wm + mt * 16 + g;
#pragma unroll
        for (int nt = 0; nt < 4; nt++) {
            int c = n0 + wn + nt * 8 + tg * 2;
            if (r0 < NN)
                *(float2*)(C + (size_t)r0 * HC + c) = make_float2(acc[mt][nt][0], acc[mt][nt][1]);
            if (r0 + 8 < NN)
                *(float2*)(C + (size_t)(r0 + 8) * HC + c) = make_float2(acc[mt][nt][2], acc[mt][nt][3]);
        }
    }
}

// ----------------------------- per-node head logits --------------------------
__global__ void k_sd(const float* __restrict__ as_, const float* __restrict__ ad_) {
    int gw = (blockIdx.x * blockDim.x + threadIdx.x) >> 5;
    int lane = threadIdx.x & 31;
    if (gw >= NN) return;
    const float* hr = g_h + (size_t)gw * HC;
    float ps[NH], pd[NH];
#pragma unroll
    for (int h = 0; h < NH; h++) {
        float v0 = hr[h * 64 + lane];
        float v1 = hr[h * 64 + 32 + lane];
        ps[h] = v0 * __ldg(as_ + h * 64 + lane) + v1 * __ldg(as_ + h * 64 + 32 + lane);
        pd[h] = v0 * __ldg(ad_ + h * 64 + lane) + v1 * __ldg(ad_ + h * 64 + 32 + lane);
    }
#pragma unroll
    for (int off = 16; off; off >>= 1)
#pragma unroll
        for (int h = 0; h < NH; h++) {
            ps[h] += __shfl_xor_sync(0xffffffffu, ps[h], off);
            pd[h] += __shfl_xor_sync(0xffffffffu, pd[h], off);
        }
    if (lane < NH) {
        g_s[gw * NH + lane] = ps[lane];
        g_dv[gw * NH + lane] = pd[lane];
    }
}

// ----------------------------- fused GAT aggregation (warp per dst) ----------
__global__ __launch_bounds__(256) void k_gat(void) {
    int n = (blockIdx.x * blockDim.x + threadIdx.x) >> 5;
    int lane = threadIdx.x & 31;
    if (n >= NN) return;
    int p0 = __ldg(&g_segoff[n]);
    int p1 = __ldg(&g_segoff[n + 1]);
    float4 d4 = *(const float4*)(g_dv + n * NH);

    // phase 1: denominator (softmax without max-shift; scale-invariant)
    float4 den = make_float4(0.f, 0.f, 0.f, 0.f);
    for (int p = p0; p < p1; p++) {
        int s = __ldg(&g_ssrc[p]);
        float4 sv = *(const float4*)(g_s + s * NH);
        den.x += __expf(lrelu(sv.x + d4.x, 0.2f));
        den.y += __expf(lrelu(sv.y + d4.y, 0.2f));
        den.z += __expf(lrelu(sv.z + d4.z, 0.2f));
        den.w += __expf(lrelu(sv.w + d4.w, 0.2f));
    }
    float4 inv = make_float4(1.f / den.x, 1.f / den.y, 1.f / den.z, 1.f / den.w);

    // per-lane head selection: q0=lane (heads 0/1), q1=lane+32 (heads 2/3)
    const bool hi = (lane >= 16);
    const float inv0 = hi ? inv.y : inv.x;
    const float inv1 = hi ? inv.w : inv.z;

    float4 accA = make_float4(0.f, 0.f, 0.f, 0.f);
    float4 accB = make_float4(0.f, 0.f, 0.f, 0.f);
    for (int p = p0; p < p1; p++) {
        int s = __ldg(&g_ssrc[p]);
        float4 sv = *(const float4*)(g_s + s * NH);
        float w0 = __expf(lrelu((hi ? sv.y + d4.y : sv.x + d4.x), 0.2f));
        float w1 = __expf(lrelu((hi ? sv.w + d4.w : sv.z + d4.z), 0.2f));
        float a0 = w0 * inv0;
        float a1 = w1 * inv1;
        const float4* hp = (const float4*)(g_h + (size_t)s * HC);
        float4 v0 = __ldg(hp + lane);
        float4 v1 = __ldg(hp + lane + 32);
        accA.x = fmaf(a0, v0.x, accA.x); accA.y = fmaf(a0, v0.y, accA.y);
        accA.z = fmaf(a0, v0.z, accA.z); accA.w = fmaf(a0, v0.w, accA.w);
        accB.x = fmaf(a1, v1.x, accB.x); accB.y = fmaf(a1, v1.y, accB.y);
        accB.z = fmaf(a1, v1.z, accB.z); accB.w = fmaf(a1, v1.w, accB.w);
    }
    float4* op = (float4*)(g_agg + (size_t)n * HC);
    op[lane] = accA;
    op[lane + 32] = accB;
}

// ----------------------------- graph norm ------------------------------------
__global__ void k_zstat(void) {
    int c = threadIdx.x;
    g_cs[c] = 0.f;
    g_css[c] = 0.f;
}
__global__ void k_colstats(const float* __restrict__ bias, int mode) {
    int c = threadIdx.x;
    float s = 0.f, ss = 0.f;
    float bc = __ldg(bias + c);
    for (int n = blockIdx.x; n < NN; n += gridDim.x) {
        float v;
        if (mode == 0) {
            v = g_agg[(size_t)n * HC + c] + bc;
        } else {
            const float* r = g_agg + (size_t)n * HC;
            v = 0.25f * (r[c] + r[c + 64] + r[c + 128] + r[c + 192]) + bc;
        }
        s += v; ss += v * v;
    }
    atomicAdd(&g_cs[c], s);
    atomicAdd(&g_css[c], ss);
}
__global__ void k_scale(const float* __restrict__ ga, const float* __restrict__ gw,
                        const float* __restrict__ gb) {
    int c = threadIdx.x;
    float inv_n = 1.0f / (float)NN;
    float mu = g_cs[c] * inv_n;
    float ex2 = g_css[c] * inv_n;
    float a = ga[c];
    float var = ex2 - 2.f * a * mu * mu + a * a * mu * mu;
    float inv = rsqrtf(var + 1e-5f);
    float sc = gw[c] * inv;
    g_scale[c] = sc;
    g_shift[c] = gb[c] - sc * a * mu;
}
__global__ void k_norm(const float* __restrict__ bias, int mode) {
    int i = blockIdx.x * blockDim.x + threadIdx.x;
    int D = mode == 0 ? HC : 64;
    if (i >= NN * D) return;
    int c = i % D;
    float v;
    if (mode == 0) {
        v = g_agg[i] + __ldg(bias + c);
    } else {
        int n = i / D;
        const float* r = g_agg + (size_t)n * HC;
        v = 0.25f * (r[c] + r[c + 64] + r[c + 128] + r[c + 192]) + __ldg(bias + c);
    }
    float y = lrelu(v * g_scale[c] + g_shift[c], 0.01f);
    if (mode == 0) {
        __nv_bfloat16 h = __float2bfloat16(y);
        g_Ah[i] = h;
        g_Al[i] = __float2bfloat16(y - __bfloat162float(h));
    } else {
        g_act[i] = y;
    }
}

// ----------------------------- MLP -------------------------------------------
template <int DI, int DO, bool RELU>
__global__ void k_fc(const float* __restrict__ in, const float* __restrict__ W,
                     const float* __restrict__ b, float* __restrict__ out) {
    __shared__ float Ws[DI * DO];
    for (int i = threadIdx.x; i < DI * DO; i += blockDim.x) Ws[i] = W[i];
    __syncthreads();
    const int npb = 256 / DO;
    int node = blockIdx.x * npb + threadIdx.x / DO;
    int o = threadIdx.x % DO;
    if (node >= NN) return;
    const float* r = in + (size_t)node * DI;
    float acc = b[o];
#pragma unroll 8
    for (int i = 0; i < DI; i++) acc = fmaf(r[i], Ws[i * DO + o], acc);
    if (RELU) acc = fmaxf(acc, 0.f);
    out[(size_t)node * DO + o] = acc;
}

// ----------------------------- driver ----------------------------------------
extern "C" void kernel_launch(void* const* d_in, const int* in_sizes, int n_in,
                              void* d_out, int out_size) {
    const float* x  = (const float*)d_in[0];
    const void*  ei = d_in[1];
    const float* W[3]   = { (const float*)d_in[2],  (const float*)d_in[9],  (const float*)d_in[16] };
    const float* as_[3] = { (const float*)d_in[3],  (const float*)d_in[10], (const float*)d_in[17] };
    const float* ad_[3] = { (const float*)d_in[4],  (const float*)d_in[11], (const float*)d_in[18] };
    const float* b_[3]  = { (const float*)d_in[5],  (const float*)d_in[12], (const float*)d_in[19] };
    const float* gw_[3] = { (const float*)d_in[6],  (const float*)d_in[13], (const float*)d_in[20] };
    const float* gb_[3] = { (const float*)d_in[7],  (const float*)d_in[14], (const float*)d_in[21] };
    const float* ga_[3] = { (const float*)d_in[8],  (const float*)d_in[15], (const float*)d_in[22] };
    const float* mW0 = (const float*)d_in[23]; const float* mb0 = (const float*)d_in[24];
    const float* mW1 = (const float*)d_in[25]; const float* mb1 = (const float*)d_in[26];
    const float* mW2 = (const float*)d_in[27]; const float* mb2 = (const float*)d_in[28];
    float* out = (float*)d_out;

    float* d_h;   cudaGetSymbolAddress((void**)&d_h,   g_h);
    float* d_act; cudaGetSymbolAddress((void**)&d_act, g_act);
    float* d_m1;  cudaGetSymbolAddress((void**)&d_m1,  g_m1);
    float* d_m2;  cudaGetSymbolAddress((void**)&d_m2,  g_m2);
    __nv_bfloat16* d_Ah;  cudaGetSymbolAddress((void**)&d_Ah,  g_Ah);
    __nv_bfloat16* d_Al;  cudaGetSymbolAddress((void**)&d_Al,  g_Al);
    __nv_bfloat16* d_WTh; cudaGetSymbolAddress((void**)&d_WTh, g_WTh);
    __nv_bfloat16* d_WTl; cudaGetSymbolAddress((void**)&d_WTl, g_WTl);

    k_detect<<<1, 1>>>(ei);
    k_convert<<<(2 * EE + 255) / 256, 256>>>(ei);

    // counting sort by dst (layer-invariant)
    k_zcnt<<<(NN + 255) / 256, 256>>>();
    k_hist<<<(EPN + 255) / 256, 256>>>();
    k_scan1<<<NSCB, 256>>>();
    k_scan2<<<1, 256>>>();
    k_scan3<<<(NN + 255) / 256, 256>>>();
    k_scatter<<<(EPN + 255) / 256, 256>>>();

    for (int L = 0; L < 3; L++) k_prep_w<<<256, 256>>>(W[L], L);
    k_convx<<<(NN * HC + 255) / 256, 256>>>(x);

    const int GB = (NN + 127) / 128;
    for (int L = 0; L < 3; L++) {
        k_gemm_mma<<<dim3(GB, 4), 256>>>(d_Ah, d_Al,
                                         d_WTh + (size_t)L * 65536, d_WTl + (size_t)L * 65536,
                                         d_h);
        k_sd<<<(NN * 32 + 255) / 256, 256>>>(as_[L], ad_[L]);
        k_gat<<<(NN * 32 + 255) / 256, 256>>>();
        int mode = (L == 2) ? 1 : 0;
        int D = (L == 2) ? 64 : HC;
        k_zstat<<<1, D>>>();
        k_colstats<<<256, D>>>(b_[L], mode);
        k_scale<<<1, D>>>(ga_[L], gw_[L], gb_[L]);
        k_norm<<<(NN * D + 255) / 256, 256>>>(b_[L], mode);
    }

    // MLP: dims [64, 32, 16, 2]
    k_fc<64, 32, true ><<<(NN + 7) / 8,   256>>>(d_act, mW0, mb0, d_m1);
    k_fc<32, 16, true ><<<(NN + 15) / 16, 256>>>(d_m1,  mW1, mb1, d_m2);
    k_fc<16, 2,  false><<<(NN + 127) / 128, 256>>>(d_m2, mW2, mb2, out);
}

// round 14
// speedup vs baseline: 2.3991x; 1.4988x over previous
#include <cuda_runtime.h>
#include <cuda_bf16.h>
#include <cstdint>

#define NN 50000
#define EE 800000
#define EPN (EE + NN)
#define HC 256
#define NH 4
#define NSCB 196

// ----------------------------- scratch ---------------------------------------
__device__ int g_is64;
__device__ int g_src[EE];
__device__ int g_dst[EE];
__device__ int g_cnt[NN];
__device__ int g_loc[NN];
__device__ int g_bsum[256];
__device__ int g_bpre[256];
__device__ int g_segoff[NN + 1];
__device__ int g_fill[NN];
__device__ int g_ssrc[EPN];
__device__ __align__(16) float    g_h[NN * HC];
__device__ __align__(16) float    g_agg[NN * HC];
__device__ __align__(16) float    g_act[NN * HC];
__device__ __align__(16) __nv_bfloat16 g_WTh[3 * 256 * 256];
__device__ __align__(16) __nv_bfloat16 g_WTl[3 * 256 * 256];
__device__ __align__(16) float    g_s[NN * NH];
__device__ __align__(16) float    g_dv[NN * NH];
__device__ float g_cs[HC], g_css[HC], g_scale[HC], g_shift[HC];
__device__ __align__(16) float g_m1[NN * 32];
__device__ __align__(16) float g_m2[NN * 16];

// ----------------------------- helpers ---------------------------------------
__device__ __forceinline__ float lrelu(float x, float s) { return x > 0.f ? x : s * x; }
__device__ __forceinline__ void red_add(float* p, float v) {
    asm volatile("red.global.add.f32 [%0], %1;" :: "l"(p), "f"(v) : "memory");
}
__device__ __forceinline__ uint32_t s2u(const void* p) {
    uint32_t a;
    asm("{ .reg .u64 t; cvta.to.shared.u64 t, %1; cvt.u32.u64 %0, t; }" : "=r"(a) : "l"(p));
    return a;
}
__device__ __forceinline__ void ldsm4(uint32_t* r, uint32_t addr) {
    asm volatile("ldmatrix.sync.aligned.m8n8.x4.shared.b16 {%0,%1,%2,%3}, [%4];"
                 : "=r"(r[0]), "=r"(r[1]), "=r"(r[2]), "=r"(r[3]) : "r"(addr));
}
__device__ __forceinline__ void mma16816(float* d, const uint32_t* a, const uint32_t* b) {
    asm volatile("mma.sync.aligned.m16n8k16.row.col.f32.bf16.bf16.f32 "
                 "{%0,%1,%2,%3},{%4,%5,%6,%7},{%8,%9},{%0,%1,%2,%3};"
                 : "+f"(d[0]), "+f"(d[1]), "+f"(d[2]), "+f"(d[3])
                 : "r"(a[0]), "r"(a[1]), "r"(a[2]), "r"(a[3]), "r"(b[0]), "r"(b[1]));
}
// pack 2 floats to bf16x2 (hi) and return residuals
__device__ __forceinline__ uint32_t pack_hi(float a, float b, float& ra, float& rb) {
    __nv_bfloat16 ha = __float2bfloat16(a), hb = __float2bfloat16(b);
    ra = a - __bfloat162float(ha);
    rb = b - __bfloat162float(hb);
    return ((uint32_t)__bfloat16_as_ushort(hb) << 16) | (uint32_t)__bfloat16_as_ushort(ha);
}
__device__ __forceinline__ uint32_t pack_lo(float ra, float rb) {
    __nv_bfloat16 la = __float2bfloat16(ra), lb = __float2bfloat16(rb);
    return ((uint32_t)__bfloat16_as_ushort(lb) << 16) | (uint32_t)__bfloat16_as_ushort(la);
}

// ----------------------------- index detect/convert --------------------------
__global__ void k_detect(const void* p) {
    const long long* q = (const long long*)p;
    int ok = 1;
    for (int i = 0; i < 8; i++) {
        long long v = q[i];
        if (v < 0 || v >= NN) ok = 0;
    }
    g_is64 = ok;
}
__global__ void k_convert(const void* p) {
    int i = blockIdx.x * blockDim.x + threadIdx.x;
    if (i >= 2 * EE) return;
    long long v = g_is64 ? ((const long long*)p)[i] : (long long)(((const int*)p)[i]);
    int x = (int)v;
    if (i < EE) g_src[i] = x; else g_dst[i - EE] = x;
}

// ----------------------------- dst counting sort ------------------------------
__global__ void k_zcnt(void) {
    int i = blockIdx.x * blockDim.x + threadIdx.x;
    if (i < NN) g_cnt[i] = 0;
}
__global__ void k_hist(void) {
    int t = blockIdx.x * blockDim.x + threadIdx.x;
    if (t >= EPN) return;
    int d = (t < EE) ? g_dst[t] : t - EE;
    atomicAdd(&g_cnt[d], 1);
}
__global__ void k_scan1(void) {
    __shared__ int sh[256];
    int t = threadIdx.x, b = blockIdx.x;
    int i = b * 256 + t;
    int v = (i < NN) ? g_cnt[i] : 0;
    sh[t] = v;
    __syncthreads();
#pragma unroll
    for (int off = 1; off < 256; off <<= 1) {
        int add = (t >= off) ? sh[t - off] : 0;
        __syncthreads();
        sh[t] += add;
        __syncthreads();
    }
    if (i < NN) g_loc[i] = sh[t] - v;
    if (t == 255) g_bsum[b] = sh[t];
}
__global__ void k_scan2(void) {
    __shared__ int sh[256];
    int t = threadIdx.x;
    int v = (t < NSCB) ? g_bsum[t] : 0;
    sh[t] = v;
    __syncthreads();
#pragma unroll
    for (int off = 1; off < 256; off <<= 1) {
        int add = (t >= off) ? sh[t - off] : 0;
        __syncthreads();
        sh[t] += add;
        __syncthreads();
    }
    g_bpre[t] = sh[t] - v;
}
__global__ void k_scan3(void) {
    int i = blockIdx.x * blockDim.x + threadIdx.x;
    if (i >= NN) return;
    int off = g_loc[i] + g_bpre[i >> 8];
    g_segoff[i] = off;
    g_fill[i] = off;
    if (i == 0) g_segoff[NN] = EPN;
}
__global__ void k_scatter(void) {
    int t = blockIdx.x * blockDim.x + threadIdx.x;
    if (t >= EPN) return;
    int s, d;
    if (t < EE) { s = g_src[t]; d = g_dst[t]; } else { s = t - EE; d = s; }
    int pos = atomicAdd(&g_fill[d], 1);
    g_ssrc[pos] = s;
}

// ----------------------------- weight split -----------------------------------
__global__ void k_prep_w(const float* __restrict__ W, int L) {
    int n = blockIdx.x, k = threadIdx.x;
    float w = W[k * 256 + n];
    size_t o = (size_t)L * 65536 + n * 256 + k;
    __nv_bfloat16 h = __float2bfloat16(w);
    g_WTh[o] = h;
    g_WTl[o] = __float2bfloat16(w - __bfloat162float(h));
}

// ----------------------------- per-layer zero (s, dv, stats) -----------------
__global__ void k_zsd(void) {
    int i = blockIdx.x * blockDim.x + threadIdx.x;
    if (i < NN * NH) { g_s[i] = 0.f; g_dv[i] = 0.f; }
    if (i < HC) { g_cs[i] = 0.f; g_css[i] = 0.f; }
}

// ----------------------------- mma.sync GEMM + fused s/d ---------------------
// C[NN,256] = act(A) * W. AFF: A = lrelu(Asrc*scale+shift) (norm fused).
// Epilogue computes per-head logits s,d for this y-block's head via red.add.
#define KCH 32
#define ROWB 80
#define OA_H 0
#define OA_L (OA_H + 128 * ROWB)
#define OB_H (OA_L + 128 * ROWB)
#define OB_L (OB_H + 64 * ROWB)
#define SMEM_SZ (OB_L + 64 * ROWB)

template <bool AFF>
__global__ __launch_bounds__(256) void k_gemm(
    const float* __restrict__ Asrc,
    const __nv_bfloat16* __restrict__ Bh, const __nv_bfloat16* __restrict__ Bl,
    const float* __restrict__ as_, const float* __restrict__ ad_,
    float* __restrict__ C) {
    __shared__ __align__(16) char smem[SMEM_SZ];
    const uint32_t sb = s2u(smem);
    const int tid = threadIdx.x;
    const int wid = tid >> 5, lane = tid & 31;
    const int m0 = blockIdx.x * 128;
    const int n0 = blockIdx.y * 64;
    const int wm = (wid >> 1) * 32;
    const int wn = (wid & 1) * 32;

    float acc[2][4][4];
#pragma unroll
    for (int i = 0; i < 2; i++)
#pragma unroll
        for (int j = 0; j < 4; j++)
#pragma unroll
            for (int q = 0; q < 4; q++) acc[i][j][q] = 0.f;

    const int lq = lane >> 3, lr = lane & 7;

    for (int ch = 0; ch < 8; ch++) {
        const int k0 = ch * KCH;
        __syncthreads();
        // A: 128 rows x 32 cols, fp32 source -> on-the-fly affine + hi/lo split
#pragma unroll
        for (int s = tid; s < 512; s += 256) {
            int r = s >> 2, kq = s & 3;
            int gr = m0 + r;
            int c0 = k0 + kq * 8;
            float v[8];
            if (gr < NN) {
                const float4* ap = (const float4*)(Asrc + (size_t)gr * HC + c0);
                float4 f0 = ap[0], f1 = ap[1];
                v[0] = f0.x; v[1] = f0.y; v[2] = f0.z; v[3] = f0.w;
                v[4] = f1.x; v[5] = f1.y; v[6] = f1.z; v[7] = f1.w;
                if (AFF) {
#pragma unroll
                    for (int j = 0; j < 8; j++)
                        v[j] = lrelu(fmaf(v[j], g_scale[c0 + j], g_shift[c0 + j]), 0.01f);
                }
            } else {
#pragma unroll
                for (int j = 0; j < 8; j++) v[j] = 0.f;
            }
            uint32_t ph[4], pl[4];
#pragma unroll
            for (int j = 0; j < 4; j++) {
                float ra, rb;
                ph[j] = pack_hi(v[2 * j], v[2 * j + 1], ra, rb);
                pl[j] = pack_lo(ra, rb);
            }
            *(uint4*)(smem + OA_H + r * ROWB + kq * 16) = make_uint4(ph[0], ph[1], ph[2], ph[3]);
            *(uint4*)(smem + OA_L + r * ROWB + kq * 16) = make_uint4(pl[0], pl[1], pl[2], pl[3]);
        }
        // B
        {
            int r = tid >> 2, kq = tid & 3;
            uint4 vh = *(const uint4*)(Bh + (size_t)(n0 + r) * HC + k0 + kq * 8);
            uint4 vl = *(const uint4*)(Bl + (size_t)(n0 + r) * HC + k0 + kq * 8);
            *(uint4*)(smem + OB_H + r * ROWB + kq * 16) = vh;
            *(uint4*)(smem + OB_L + r * ROWB + kq * 16) = vl;
        }
        __syncthreads();

#pragma unroll
        for (int ks = 0; ks < 2; ks++) {
            uint32_t ah[2][4], al[2][4], bh[2][4], bl[2][4];
#pragma unroll
            for (int mt = 0; mt < 2; mt++) {
                int row = wm + mt * 16 + (lq & 1) * 8 + lr;
                int u = ks * 2 + (lq >> 1);
                ldsm4(ah[mt], sb + OA_H + row * ROWB + u * 16);
                ldsm4(al[mt], sb + OA_L + row * ROWB + u * 16);
            }
#pragma unroll
            for (int p = 0; p < 2; p++) {
                int n = wn + p * 16 + (lq >> 1) * 8 + lr;
                int u = ks * 2 + (lq & 1);
                ldsm4(bh[p], sb + OB_H + n * ROWB + u * 16);
                ldsm4(bl[p], sb + OB_L + n * ROWB + u * 16);
            }
#pragma unroll
            for (int mt = 0; mt < 2; mt++)
#pragma unroll
                for (int nt = 0; nt < 4; nt++) {
                    const uint32_t* ph = &bh[nt >> 1][(nt & 1) * 2];
                    const uint32_t* pl = &bl[nt >> 1][(nt & 1) * 2];
                    mma16816(acc[mt][nt], ah[mt], ph);
                    mma16816(acc[mt][nt], ah[mt], pl);
                    mma16816(acc[mt][nt], al[mt], ph);
                }
        }
    }

    const int g = lane >> 2, tg = lane & 3;
    // C store
#pragma unroll
    for (int mt = 0; mt < 2; mt++) {
        int r0 = m0 + wm + mt * 16 + g;
#pragma unroll
        for (int nt = 0; nt < 4; nt++) {
            int c = n0 + wn + nt * 8 + tg * 2;
            if (r0 < NN)
                *(float2*)(C + (size_t)r0 * HC + c) = make_float2(acc[mt][nt][0], acc[mt][nt][1]);
            if (r0 + 8 < NN)
                *(float2*)(C + (size_t)(r0 + 8) * HC + c) = make_float2(acc[mt][nt][2], acc[mt][nt][3]);
        }
    }

    // fused per-head logits: this y-block == head blockIdx.y
    const int head = blockIdx.y;
    float s_part[4] = {0.f, 0.f, 0.f, 0.f}, d_part[4] = {0.f, 0.f, 0.f, 0.f};
#pragma unroll
    for (int mt = 0; mt < 2; mt++)
#pragma unroll
        for (int nt = 0; nt < 4; nt++) {
            int c = wn + nt * 8 + tg * 2;           // within-head column
            float a0 = __ldg(as_ + head * 64 + c), a1 = __ldg(as_ + head * 64 + c + 1);
            float e0 = __ldg(ad_ + head * 64 + c), e1 = __ldg(ad_ + head * 64 + c + 1);
            s_part[mt * 2 + 0] += acc[mt][nt][0] * a0 + acc[mt][nt][1] * a1;
            s_part[mt * 2 + 1] += acc[mt][nt][2] * a0 + acc[mt][nt][3] * a1;
            d_part[mt * 2 + 0] += acc[mt][nt][0] * e0 + acc[mt][nt][1] * e1;
            d_part[mt * 2 + 1] += acc[mt][nt][2] * e0 + acc[mt][nt][3] * e1;
        }
#pragma unroll
    for (int off = 1; off < 4; off <<= 1)
#pragma unroll
        for (int r = 0; r < 4; r++) {
            s_part[r] += __shfl_xor_sync(0xffffffffu, s_part[r], off);
            d_part[r] += __shfl_xor_sync(0xffffffffu, d_part[r], off);
        }
    if (tg == 0) {
#pragma unroll
        for (int r = 0; r < 4; r++) {
            int row = m0 + wm + (r >> 1) * 16 + g + (r & 1) * 8;
            if (row < NN) {
                red_add(&g_s[row * NH + head], s_part[r]);
                red_add(&g_dv[row * NH + head], d_part[r]);
            }
        }
    }
}

// ----------------------------- fused GAT aggregation + stats -----------------
// warp per dst node; 8 nodes per block (50000 = 6250*8 exactly).
__global__ __launch_bounds__(256) void k_gat(const float* __restrict__ bias, int mode) {
    __shared__ float sv[8][256];
    int n = (blockIdx.x * blockDim.x + threadIdx.x) >> 5;
    int lane = threadIdx.x & 31;
    int wz = threadIdx.x >> 5;
    int p0 = __ldg(&g_segoff[n]);
    int p1 = __ldg(&g_segoff[n + 1]);
    float4 d4 = *(const float4*)(g_dv + n * NH);

    float4 den = make_float4(0.f, 0.f, 0.f, 0.f);
    for (int p = p0; p < p1; p++) {
        int s = __ldg(&g_ssrc[p]);
        float4 sval = *(const float4*)(g_s + s * NH);
        den.x += __expf(lrelu(sval.x + d4.x, 0.2f));
        den.y += __expf(lrelu(sval.y + d4.y, 0.2f));
        den.z += __expf(lrelu(sval.z + d4.z, 0.2f));
        den.w += __expf(lrelu(sval.w + d4.w, 0.2f));
    }
    float4 inv = make_float4(1.f / den.x, 1.f / den.y, 1.f / den.z, 1.f / den.w);

    const bool hi = (lane >= 16);
    const float inv0 = hi ? inv.y : inv.x;
    const float inv1 = hi ? inv.w : inv.z;

    float4 accA = make_float4(0.f, 0.f, 0.f, 0.f);
    float4 accB = make_float4(0.f, 0.f, 0.f, 0.f);
    for (int p = p0; p < p1; p++) {
        int s = __ldg(&g_ssrc[p]);
        float4 sval = *(const float4*)(g_s + s * NH);
        float w0 = __expf(lrelu((hi ? sval.y + d4.y : sval.x + d4.x), 0.2f));
        float w1 = __expf(lrelu((hi ? sval.w + d4.w : sval.z + d4.z), 0.2f));
        float a0 = w0 * inv0;
        float a1 = w1 * inv1;
        const float4* hp = (const float4*)(g_h + (size_t)s * HC);
        float4 v0 = __ldg(hp + lane);
        float4 v1 = __ldg(hp + lane + 32);
        accA.x = fmaf(a0, v0.x, accA.x); accA.y = fmaf(a0, v0.y, accA.y);
        accA.z = fmaf(a0, v0.z, accA.z); accA.w = fmaf(a0, v0.w, accA.w);
        accB.x = fmaf(a1, v1.x, accB.x); accB.y = fmaf(a1, v1.y, accB.y);
        accB.z = fmaf(a1, v1.z, accB.z); accB.w = fmaf(a1, v1.w, accB.w);
    }

    if (mode == 0) {
        float4* op = (float4*)(g_agg + (size_t)n * HC);
        op[lane] = accA;
        op[lane + 32] = accB;
        // stats staging: v = agg + bias
        float4 bA = __ldg(((const float4*)bias) + lane);
        float4 bB = __ldg(((const float4*)bias) + lane + 32);
        *(float4*)&sv[wz][lane * 4] = make_float4(accA.x + bA.x, accA.y + bA.y,
                                                  accA.z + bA.z, accA.w + bA.w);
        *(float4*)&sv[wz][(lane + 32) * 4] = make_float4(accB.x + bB.x, accB.y + bB.y,
                                                         accB.z + bB.z, accB.w + bB.w);
        __syncthreads();
        int c = threadIdx.x;
        float s = 0.f, ss = 0.f;
#pragma unroll
        for (int w = 0; w < 8; w++) {
            float xv = sv[w][c];
            s += xv; ss += xv * xv;
        }
        red_add(&g_cs[c], s);
        red_add(&g_css[c], ss);
    } else {
        // head-mean: combine cols across (accA,accB) and lanes xor 16
        float4 tA, tB;
        tA.x = __shfl_xor_sync(0xffffffffu, accA.x, 16);
        tA.y = __shfl_xor_sync(0xffffffffu, accA.y, 16);
        tA.z = __shfl_xor_sync(0xffffffffu, accA.z, 16);
        tA.w = __shfl_xor_sync(0xffffffffu, accA.w, 16);
        tB.x = __shfl_xor_sync(0xffffffffu, accB.x, 16);
        tB.y = __shfl_xor_sync(0xffffffffu, accB.y, 16);
        tB.z = __shfl_xor_sync(0xffffffffu, accB.z, 16);
        tB.w = __shfl_xor_sync(0xffffffffu, accB.w, 16);
        if (!hi) {
            float4 m = make_float4(0.25f * (accA.x + tA.x + accB.x + tB.x),
                                   0.25f * (accA.y + tA.y + accB.y + tB.y),
                                   0.25f * (accA.z + tA.z + accB.z + tB.z),
                                   0.25f * (accA.w + tA.w + accB.w + tB.w));
            *(float4*)(g_act + (size_t)n * 64 + lane * 4) = m;
            float4 b4 = __ldg(((const float4*)bias) + lane);
            *(float4*)&sv[wz][lane * 4] = make_float4(m.x + b4.x, m.y + b4.y,
                                                      m.z + b4.z, m.w + b4.w);
        }
        __syncthreads();
        int c = threadIdx.x;
        if (c < 64) {
            float s = 0.f, ss = 0.f;
#pragma unroll
            for (int w = 0; w < 8; w++) {
                float xv = sv[w][c];
                s += xv; ss += xv * xv;
            }
            red_add(&g_cs[c], s);
            red_add(&g_css[c], ss);
        }
    }
}

// ----------------------------- scale (folds bias into shift) -----------------
__global__ void k_scale(const float* __restrict__ ga, const float* __restrict__ gw,
                        const float* __restrict__ gb, const float* __restrict__ bias) {
    int c = threadIdx.x;
    float inv_n = 1.0f / (float)NN;
    float mu = g_cs[c] * inv_n;
    float ex2 = g_css[c] * inv_n;
    float a = ga[c];
    float var = ex2 - 2.f * a * mu * mu + a * a * mu * mu;
    float inv = rsqrtf(var + 1e-5f);
    float sc = gw[c] * inv;
    g_scale[c] = sc;
    g_shift[c] = gb[c] - sc * a * mu + sc * bias[c];
}

// ----------------------------- final 64-wide norm (L2 only, in place) --------
__global__ void k_norm64(void) {
    int i = blockIdx.x * blockDim.x + threadIdx.x;
    if (i >= NN * 64) return;
    int c = i & 63;
    g_act[i] = lrelu(fmaf(g_act[i], g_scale[c], g_shift[c]), 0.01f);
}

// ----------------------------- MLP -------------------------------------------
template <int DI, int DO, bool RELU>
__global__ void k_fc(const float* __restrict__ in, const float* __restrict__ W,
                     const float* __restrict__ b, float* __restrict__ out) {
    __shared__ float Ws[DI * DO];
    for (int i = threadIdx.x; i < DI * DO; i += blockDim.x) Ws[i] = W[i];
    __syncthreads();
    const int npb = 256 / DO;
    int node = blockIdx.x * npb + threadIdx.x / DO;
    int o = threadIdx.x % DO;
    if (node >= NN) return;
    const float* r = in + (size_t)node * DI;
    float acc = b[o];
#pragma unroll 8
    for (int i = 0; i < DI; i++) acc = fmaf(r[i], Ws[i * DO + o], acc);
    if (RELU) acc = fmaxf(acc, 0.f);
    out[(size_t)node * DO + o] = acc;
}

// ----------------------------- driver ----------------------------------------
extern "C" void kernel_launch(void* const* d_in, const int* in_sizes, int n_in,
                              void* d_out, int out_size) {
    const float* x  = (const float*)d_in[0];
    const void*  ei = d_in[1];
    const float* W[3]   = { (const float*)d_in[2],  (const float*)d_in[9],  (const float*)d_in[16] };
    const float* as_[3] = { (const float*)d_in[3],  (const float*)d_in[10], (const float*)d_in[17] };
    const float* ad_[3] = { (const float*)d_in[4],  (const float*)d_in[11], (const float*)d_in[18] };
    const float* b_[3]  = { (const float*)d_in[5],  (const float*)d_in[12], (const float*)d_in[19] };
    const float* gw_[3] = { (const float*)d_in[6],  (const float*)d_in[13], (const float*)d_in[20] };
    const float* gb_[3] = { (const float*)d_in[7],  (const float*)d_in[14], (const float*)d_in[21] };
    const float* ga_[3] = { (const float*)d_in[8],  (const float*)d_in[15], (const float*)d_in[22] };
    const float* mW0 = (const float*)d_in[23]; const float* mb0 = (const float*)d_in[24];
    const float* mW1 = (const float*)d_in[25]; const float* mb1 = (const float*)d_in[26];
    const float* mW2 = (const float*)d_in[27]; const float* mb2 = (const float*)d_in[28];
    float* out = (float*)d_out;

    float* d_h;   cudaGetSymbolAddress((void**)&d_h,   g_h);
    float* d_agg; cudaGetSymbolAddress((void**)&d_agg, g_agg);
    float* d_act; cudaGetSymbolAddress((void**)&d_act, g_act);
    float* d_m1;  cudaGetSymbolAddress((void**)&d_m1,  g_m1);
    float* d_m2;  cudaGetSymbolAddress((void**)&d_m2,  g_m2);
    __nv_bfloat16* d_WTh; cudaGetSymbolAddress((void**)&d_WTh, g_WTh);
    __nv_bfloat16* d_WTl; cudaGetSymbolAddress((void**)&d_WTl, g_WTl);

    k_detect<<<1, 1>>>(ei);
    k_convert<<<(2 * EE + 255) / 256, 256>>>(ei);

    // counting sort by dst
    k_zcnt<<<(NN + 255) / 256, 256>>>();
    k_hist<<<(EPN + 255) / 256, 256>>>();
    k_scan1<<<NSCB, 256>>>();
    k_scan2<<<1, 256>>>();
    k_scan3<<<(NN + 255) / 256, 256>>>();
    k_scatter<<<(EPN + 255) / 256, 256>>>();

    for (int L = 0; L < 3; L++) k_prep_w<<<256, 256>>>(W[L], L);

    const int GB = (NN + 127) / 128;
    for (int L = 0; L < 3; L++) {
        k_zsd<<<(NN * NH + 255) / 256, 256>>>();
        const float* Asrc = (L == 0) ? x : d_agg;
        if (L == 0)
            k_gemm<false><<<dim3(GB, 4), 256>>>(Asrc, d_WTh + (size_t)L * 65536,
                                                d_WTl + (size_t)L * 65536, as_[L], ad_[L], d_h);
        else
            k_gemm<true><<<dim3(GB, 4), 256>>>(Asrc, d_WTh + (size_t)L * 65536,
                                               d_WTl + (size_t)L * 65536, as_[L], ad_[L], d_h);
        int mode = (L == 2) ? 1 : 0;
        k_gat<<<(NN * 32 + 255) / 256, 256>>>(b_[L], mode);
        k_scale<<<1, (L == 2) ? 64 : 256>>>(ga_[L], gw_[L], gb_[L], b_[L]);
    }
    k_norm64<<<(NN * 64 + 255) / 256, 256>>>();

    // MLP: dims [64, 32, 16, 2]
    k_fc<64, 32, true ><<<(NN + 7) / 8,   256>>>(d_act, mW0, mb0, d_m1);
    k_fc<32, 16, true ><<<(NN + 15) / 16, 256>>>(d_m1,  mW1, mb1, d_m2);
    k_fc<16, 2,  false><<<(NN + 127) / 128, 256>>>(d_m2, mW2, mb2, out);
}

// round 15
// speedup vs baseline: 2.6905x; 1.1215x over previous
#include <cuda_runtime.h>
#include <cuda_bf16.h>
#include <cstdint>

#define NN 50000
#define EE 800000
#define EPN (EE + NN)
#define HC 256
#define NH 4
#define NSCB 196

// ----------------------------- scratch ---------------------------------------
__device__ int g_is64;
__device__ int g_src[EE];
__device__ int g_dst[EE];
__device__ int g_cnt[NN];
__device__ int g_loc[NN];
__device__ int g_bsum[256];
__device__ int g_bpre[256];
__device__ int g_segoff[NN + 1];
__device__ int g_fill[NN];
__device__ int g_ssrc[EPN];
__device__ __align__(16) float    g_h[NN * HC];
__device__ __align__(16) float    g_agg[NN * HC];
__device__ __align__(16) float    g_act[NN * 64];
__device__ __align__(16) __nv_bfloat16 g_WTh[3 * 256 * 256];
__device__ __align__(16) __nv_bfloat16 g_WTl[3 * 256 * 256];
__device__ __align__(16) float    g_s[NN * NH];
__device__ __align__(16) float    g_dv[NN * NH];
__device__ float g_cs[HC], g_css[HC], g_scale[HC], g_shift[HC];

// ----------------------------- helpers ---------------------------------------
__device__ __forceinline__ float lrelu(float x, float s) { return x > 0.f ? x : s * x; }
__device__ __forceinline__ void red_add(float* p, float v) {
    asm volatile("red.global.add.f32 [%0], %1;" :: "l"(p), "f"(v) : "memory");
}
__device__ __forceinline__ uint32_t s2u(const void* p) {
    uint32_t a;
    asm("{ .reg .u64 t; cvta.to.shared.u64 t, %1; cvt.u32.u64 %0, t; }" : "=r"(a) : "l"(p));
    return a;
}
__device__ __forceinline__ void ldsm4(uint32_t* r, uint32_t addr) {
    asm volatile("ldmatrix.sync.aligned.m8n8.x4.shared.b16 {%0,%1,%2,%3}, [%4];"
                 : "=r"(r[0]), "=r"(r[1]), "=r"(r[2]), "=r"(r[3]) : "r"(addr));
}
__device__ __forceinline__ void mma16816(float* d, const uint32_t* a, const uint32_t* b) {
    asm volatile("mma.sync.aligned.m16n8k16.row.col.f32.bf16.bf16.f32 "
                 "{%0,%1,%2,%3},{%4,%5,%6,%7},{%8,%9},{%0,%1,%2,%3};"
                 : "+f"(d[0]), "+f"(d[1]), "+f"(d[2]), "+f"(d[3])
                 : "r"(a[0]), "r"(a[1]), "r"(a[2]), "r"(a[3]), "r"(b[0]), "r"(b[1]));
}
__device__ __forceinline__ uint32_t pack_hi(float a, float b, float& ra, float& rb) {
    __nv_bfloat16 ha = __float2bfloat16(a), hb = __float2bfloat16(b);
    ra = a - __bfloat162float(ha);
    rb = b - __bfloat162float(hb);
    return ((uint32_t)__bfloat16_as_ushort(hb) << 16) | (uint32_t)__bfloat16_as_ushort(ha);
}
__device__ __forceinline__ uint32_t pack_lo(float ra, float rb) {
    __nv_bfloat16 la = __float2bfloat16(ra), lb = __float2bfloat16(rb);
    return ((uint32_t)__bfloat16_as_ushort(lb) << 16) | (uint32_t)__bfloat16_as_ushort(la);
}

// ----------------------------- index detect / convert+hist -------------------
__global__ void k_detect(const void* p) {
    const long long* q = (const long long*)p;
    int ok = 1;
    for (int i = 0; i < 8; i++) {
        long long v = q[i];
        if (v < 0 || v >= NN) ok = 0;
    }
    g_is64 = ok;
}
__global__ void k_zcnt(void) {
    int i = blockIdx.x * blockDim.x + threadIdx.x;
    if (i < NN) g_cnt[i] = 1;          // self loop pre-counted
}
__global__ void k_convhist(const void* p) {
    int i = blockIdx.x * blockDim.x + threadIdx.x;
    if (i >= 2 * EE) return;
    long long v = g_is64 ? ((const long long*)p)[i] : (long long)(((const int*)p)[i]);
    int x = (int)v;
    if (i < EE) {
        g_src[i] = x;
    } else {
        g_dst[i - EE] = x;
        atomicAdd(&g_cnt[x], 1);
    }
}

// ----------------------------- scan + scatter ---------------------------------
__global__ void k_scan1(void) {
    __shared__ int sh[256];
    int t = threadIdx.x, b = blockIdx.x;
    int i = b * 256 + t;
    int v = (i < NN) ? g_cnt[i] : 0;
    sh[t] = v;
    __syncthreads();
#pragma unroll
    for (int off = 1; off < 256; off <<= 1) {
        int add = (t >= off) ? sh[t - off] : 0;
        __syncthreads();
        sh[t] += add;
        __syncthreads();
    }
    if (i < NN) g_loc[i] = sh[t] - v;
    if (t == 255) g_bsum[b] = sh[t];
}
__global__ void k_scan2(void) {
    __shared__ int sh[256];
    int t = threadIdx.x;
    int v = (t < NSCB) ? g_bsum[t] : 0;
    sh[t] = v;
    __syncthreads();
#pragma unroll
    for (int off = 1; off < 256; off <<= 1) {
        int add = (t >= off) ? sh[t - off] : 0;
        __syncthreads();
        sh[t] += add;
        __syncthreads();
    }
    g_bpre[t] = sh[t] - v;
}
__global__ void k_scan3(void) {
    int i = blockIdx.x * blockDim.x + threadIdx.x;
    if (i >= NN) return;
    int off = g_loc[i] + g_bpre[i >> 8];
    g_segoff[i] = off;
    g_fill[i] = off;
    if (i == 0) g_segoff[NN] = EPN;
}
__global__ void k_scatter(void) {
    int t = blockIdx.x * blockDim.x + threadIdx.x;
    if (t >= EPN) return;
    int s, d;
    if (t < EE) { s = g_src[t]; d = g_dst[t]; } else { s = t - EE; d = s; }
    int pos = atomicAdd(&g_fill[d], 1);
    g_ssrc[pos] = s;
}

// ----------------------------- weight split -----------------------------------
__global__ void k_prep_w(const float* __restrict__ W, int L) {
    int n = blockIdx.x, k = threadIdx.x;
    float w = W[k * 256 + n];
    size_t o = (size_t)L * 65536 + n * 256 + k;
    __nv_bfloat16 h = __float2bfloat16(w);
    g_WTh[o] = h;
    g_WTl[o] = __float2bfloat16(w - __bfloat162float(h));
}

// ----------------------------- mma.sync GEMM + fused s/d ---------------------
#define KCH 32
#define ROWB 80
#define OA_H 0
#define OA_L (OA_H + 128 * ROWB)
#define OB_H (OA_L + 128 * ROWB)
#define OB_L (OB_H + 64 * ROWB)
#define SMEM_SZ (OB_L + 64 * ROWB)

template <bool AFF>
__global__ __launch_bounds__(256) void k_gemm(
    const float* __restrict__ Asrc,
    const __nv_bfloat16* __restrict__ Bh, const __nv_bfloat16* __restrict__ Bl,
    const float* __restrict__ as_, const float* __restrict__ ad_,
    float* __restrict__ C) {
    __shared__ __align__(16) char smem[SMEM_SZ];
    const uint32_t sb = s2u(smem);
    const int tid = threadIdx.x;
    const int wid = tid >> 5, lane = tid & 31;
    const int m0 = blockIdx.x * 128;
    const int n0 = blockIdx.y * 64;
    const int wm = (wid >> 1) * 32;
    const int wn = (wid & 1) * 32;

    float acc[2][4][4];
#pragma unroll
    for (int i = 0; i < 2; i++)
#pragma unroll
        for (int j = 0; j < 4; j++)
#pragma unroll
            for (int q = 0; q < 4; q++) acc[i][j][q] = 0.f;

    const int lq = lane >> 3, lr = lane & 7;

    for (int ch = 0; ch < 8; ch++) {
        const int k0 = ch * KCH;
        __syncthreads();
#pragma unroll
        for (int s = tid; s < 512; s += 256) {
            int r = s >> 2, kq = s & 3;
            int gr = m0 + r;
            int c0 = k0 + kq * 8;
            float v[8];
            if (gr < NN) {
                const float4* ap = (const float4*)(Asrc + (size_t)gr * HC + c0);
                float4 f0 = ap[0], f1 = ap[1];
                v[0] = f0.x; v[1] = f0.y; v[2] = f0.z; v[3] = f0.w;
                v[4] = f1.x; v[5] = f1.y; v[6] = f1.z; v[7] = f1.w;
                if (AFF) {
#pragma unroll
                    for (int j = 0; j < 8; j++)
                        v[j] = lrelu(fmaf(v[j], g_scale[c0 + j], g_shift[c0 + j]), 0.01f);
                }
            } else {
#pragma unroll
                for (int j = 0; j < 8; j++) v[j] = 0.f;
            }
            uint32_t ph[4], pl[4];
#pragma unroll
            for (int j = 0; j < 4; j++) {
                float ra, rb;
                ph[j] = pack_hi(v[2 * j], v[2 * j + 1], ra, rb);
                pl[j] = pack_lo(ra, rb);
            }
            *(uint4*)(smem + OA_H + r * ROWB + kq * 16) = make_uint4(ph[0], ph[1], ph[2], ph[3]);
            *(uint4*)(smem + OA_L + r * ROWB + kq * 16) = make_uint4(pl[0], pl[1], pl[2], pl[3]);
        }
        {
            int r = tid >> 2, kq = tid & 3;
            uint4 vh = *(const uint4*)(Bh + (size_t)(n0 + r) * HC + k0 + kq * 8);
            uint4 vl = *(const uint4*)(Bl + (size_t)(n0 + r) * HC + k0 + kq * 8);
            *(uint4*)(smem + OB_H + r * ROWB + kq * 16) = vh;
            *(uint4*)(smem + OB_L + r * ROWB + kq * 16) = vl;
        }
        __syncthreads();

#pragma unroll
        for (int ks = 0; ks < 2; ks++) {
            uint32_t ah[2][4], al[2][4], bh[2][4], bl[2][4];
#pragma unroll
            for (int mt = 0; mt < 2; mt++) {
                int row = wm + mt * 16 + (lq & 1) * 8 + lr;
                int u = ks * 2 + (lq >> 1);
                ldsm4(ah[mt], sb + OA_H + row * ROWB + u * 16);
                ldsm4(al[mt], sb + OA_L + row * ROWB + u * 16);
            }
#pragma unroll
            for (int p = 0; p < 2; p++) {
                int n = wn + p * 16 + (lq >> 1) * 8 + lr;
                int u = ks * 2 + (lq & 1);
                ldsm4(bh[p], sb + OB_H + n * ROWB + u * 16);
                ldsm4(bl[p], sb + OB_L + n * ROWB + u * 16);
            }
#pragma unroll
            for (int mt = 0; mt < 2; mt++)
#pragma unroll
                for (int nt = 0; nt < 4; nt++) {
                    const uint32_t* ph = &bh[nt >> 1][(nt & 1) * 2];
                    const uint32_t* pl = &bl[nt >> 1][(nt & 1) * 2];
                    mma16816(acc[mt][nt], ah[mt], ph);
                    mma16816(acc[mt][nt], ah[mt], pl);
                    mma16816(acc[mt][nt], al[mt], ph);
                }
        }
    }

    const int g = lane >> 2, tg = lane & 3;
    // C store
#pragma unroll
    for (int mt = 0; mt < 2; mt++) {
        int r0 = m0 + wm + mt * 16 + g;
#pragma unroll
        for (int nt = 0; nt < 4; nt++) {
            int c = n0 + wn + nt * 8 + tg * 2;
            if (r0 < NN)
                *(float2*)(C + (size_t)r0 * HC + c) = make_float2(acc[mt][nt][0], acc[mt][nt][1]);
            if (r0 + 8 < NN)
                *(float2*)(C + (size_t)(r0 + 8) * HC + c) = make_float2(acc[mt][nt][2], acc[mt][nt][3]);
        }
    }

    // fused per-head logits (head == blockIdx.y); cross-half combine in smem
    const int head = blockIdx.y;
    float s_part[4] = {0.f, 0.f, 0.f, 0.f}, d_part[4] = {0.f, 0.f, 0.f, 0.f};
#pragma unroll
    for (int mt = 0; mt < 2; mt++)
#pragma unroll
        for (int nt = 0; nt < 4; nt++) {
            int c = wn + nt * 8 + tg * 2;
            float a0 = __ldg(as_ + head * 64 + c), a1 = __ldg(as_ + head * 64 + c + 1);
            float e0 = __ldg(ad_ + head * 64 + c), e1 = __ldg(ad_ + head * 64 + c + 1);
            s_part[mt * 2 + 0] += acc[mt][nt][0] * a0 + acc[mt][nt][1] * a1;
            s_part[mt * 2 + 1] += acc[mt][nt][2] * a0 + acc[mt][nt][3] * a1;
            d_part[mt * 2 + 0] += acc[mt][nt][0] * e0 + acc[mt][nt][1] * e1;
            d_part[mt * 2 + 1] += acc[mt][nt][2] * e0 + acc[mt][nt][3] * e1;
        }
#pragma unroll
    for (int off = 1; off < 4; off <<= 1)
#pragma unroll
        for (int r = 0; r < 4; r++) {
            s_part[r] += __shfl_xor_sync(0xffffffffu, s_part[r], off);
            d_part[r] += __shfl_xor_sync(0xffffffffu, d_part[r], off);
        }
    float* sS = (float*)smem;
    float* sD = sS + 128;
    __syncthreads();                       // smem (mma staging) free for reuse
    if ((wid & 1) == 0 && tg == 0) {
#pragma unroll
        for (int r = 0; r < 4; r++) {
            int lrow = wm + (r >> 1) * 16 + g + (r & 1) * 8;
            sS[lrow] = s_part[r];
            sD[lrow] = d_part[r];
        }
    }
    __syncthreads();
    if ((wid & 1) == 1 && tg == 0) {
#pragma unroll
        for (int r = 0; r < 4; r++) {
            int lrow = wm + (r >> 1) * 16 + g + (r & 1) * 8;
            int row = m0 + lrow;
            if (row < NN) {
                g_s[row * NH + head]  = sS[lrow] + s_part[r];
                g_dv[row * NH + head] = sD[lrow] + d_part[r];
            }
        }
    }
}

// ----------------------------- fused GAT (single pass) + stats ---------------
__global__ __launch_bounds__(256) void k_gat(const float* __restrict__ bias, int mode) {
    __shared__ float sv[8][256];
    int n = (blockIdx.x * blockDim.x + threadIdx.x) >> 5;
    int lane = threadIdx.x & 31;
    int wz = threadIdx.x >> 5;
    int p0 = __ldg(&g_segoff[n]);
    int p1 = __ldg(&g_segoff[n + 1]);
    float4 d4 = *(const float4*)(g_dv + n * NH);

    const bool hi = (lane >= 16);
    float4 den = make_float4(0.f, 0.f, 0.f, 0.f);
    float4 accA = make_float4(0.f, 0.f, 0.f, 0.f);
    float4 accB = make_float4(0.f, 0.f, 0.f, 0.f);
    for (int p = p0; p < p1; p++) {
        int s = __ldg(&g_ssrc[p]);
        float4 sval = *(const float4*)(g_s + s * NH);
        float e0 = __expf(lrelu(sval.x + d4.x, 0.2f));
        float e1 = __expf(lrelu(sval.y + d4.y, 0.2f));
        float e2 = __expf(lrelu(sval.z + d4.z, 0.2f));
        float e3 = __expf(lrelu(sval.w + d4.w, 0.2f));
        den.x += e0; den.y += e1; den.z += e2; den.w += e3;
        float w0 = hi ? e1 : e0;
        float w1 = hi ? e3 : e2;
        const float4* hp = (const float4*)(g_h + (size_t)s * HC);
        float4 v0 = __ldg(hp + lane);
        float4 v1 = __ldg(hp + lane + 32);
        accA.x = fmaf(w0, v0.x, accA.x); accA.y = fmaf(w0, v0.y, accA.y);
        accA.z = fmaf(w0, v0.z, accA.z); accA.w = fmaf(w0, v0.w, accA.w);
        accB.x = fmaf(w1, v1.x, accB.x); accB.y = fmaf(w1, v1.y, accB.y);
        accB.z = fmaf(w1, v1.z, accB.z); accB.w = fmaf(w1, v1.w, accB.w);
    }
    float inv0 = 1.f / (hi ? den.y : den.x);
    float inv1 = 1.f / (hi ? den.w : den.z);
    accA.x *= inv0; accA.y *= inv0; accA.z *= inv0; accA.w *= inv0;
    accB.x *= inv1; accB.y *= inv1; accB.z *= inv1; accB.w *= inv1;

    if (mode == 0) {
        float4* op = (float4*)(g_agg + (size_t)n * HC);
        op[lane] = accA;
        op[lane + 32] = accB;
        float4 bA = __ldg(((const float4*)bias) + lane);
        float4 bB = __ldg(((const float4*)bias) + lane + 32);
        *(float4*)&sv[wz][lane * 4] = make_float4(accA.x + bA.x, accA.y + bA.y,
                                                  accA.z + bA.z, accA.w + bA.w);
        *(float4*)&sv[wz][(lane + 32) * 4] = make_float4(accB.x + bB.x, accB.y + bB.y,
                                                         accB.z + bB.z, accB.w + bB.w);
        __syncthreads();
        int c = threadIdx.x;
        float s = 0.f, ss = 0.f;
#pragma unroll
        for (int w = 0; w < 8; w++) {
            float xv = sv[w][c];
            s += xv; ss += xv * xv;
        }
        red_add(&g_cs[c], s);
        red_add(&g_css[c], ss);
    } else {
        float4 tA, tB;
        tA.x = __shfl_xor_sync(0xffffffffu, accA.x, 16);
        tA.y = __shfl_xor_sync(0xffffffffu, accA.y, 16);
        tA.z = __shfl_xor_sync(0xffffffffu, accA.z, 16);
        tA.w = __shfl_xor_sync(0xffffffffu, accA.w, 16);
        tB.x = __shfl_xor_sync(0xffffffffu, accB.x, 16);
        tB.y = __shfl_xor_sync(0xffffffffu, accB.y, 16);
        tB.z = __shfl_xor_sync(0xffffffffu, accB.z, 16);
        tB.w = __shfl_xor_sync(0xffffffffu, accB.w, 16);
        if (!hi) {
            float4 m = make_float4(0.25f * (accA.x + tA.x + accB.x + tB.x),
                                   0.25f * (accA.y + tA.y + accB.y + tB.y),
                                   0.25f * (accA.z + tA.z + accB.z + tB.z),
                                   0.25f * (accA.w + tA.w + accB.w + tB.w));
            *(float4*)(g_act + (size_t)n * 64 + lane * 4) = m;
            float4 b4 = __ldg(((const float4*)bias) + lane);
            *(float4*)&sv[wz][lane * 4] = make_float4(m.x + b4.x, m.y + b4.y,
                                                      m.z + b4.z, m.w + b4.w);
        }
        __syncthreads();
        int c = threadIdx.x;
        if (c < 64) {
            float s = 0.f, ss = 0.f;
#pragma unroll
            for (int w = 0; w < 8; w++) {
                float xv = sv[w][c];
                s += xv; ss += xv * xv;
            }
            red_add(&g_cs[c], s);
            red_add(&g_css[c], ss);
        }
    }
}

// ----------------------------- scale (folds bias; self-zeroes stats) ---------
__global__ void k_scale(const float* __restrict__ ga, const float* __restrict__ gw,
                        const float* __restrict__ gb, const float* __restrict__ bias) {
    int c = threadIdx.x;
    float inv_n = 1.0f / (float)NN;
    float mu = g_cs[c] * inv_n;
    float ex2 = g_css[c] * inv_n;
    float a = ga[c];
    float var = ex2 - 2.f * a * mu * mu + a * a * mu * mu;
    float inv = rsqrtf(var + 1e-5f);
    float sc = gw[c] * inv;
    g_scale[c] = sc;
    g_shift[c] = gb[c] - sc * a * mu + sc * bias[c];
    g_cs[c] = 0.f;              // restore zero invariant for next gat
    g_css[c] = 0.f;
}

// ----------------------------- fused norm + 3-layer MLP ----------------------
__global__ __launch_bounds__(256) void k_mlp(
    const float* __restrict__ mW0, const float* __restrict__ mb0,
    const float* __restrict__ mW1, const float* __restrict__ mb1,
    const float* __restrict__ mW2, const float* __restrict__ mb2,
    float* __restrict__ out) {
    __shared__ float W0s[64 * 32], W1s[32 * 16], W2s[16 * 2];
    __shared__ float b0s[32], b1s[16], b2s[2];
    int tid = threadIdx.x;
    for (int i = tid; i < 64 * 32; i += 256) W0s[i] = mW0[i];
    for (int i = tid; i < 32 * 16; i += 256) W1s[i] = mW1[i];
    if (tid < 32) W2s[tid] = mW2[tid];
    if (tid < 32) b0s[tid] = mb0[tid];
    if (tid < 16) b1s[tid] = mb1[tid];
    if (tid < 2)  b2s[tid] = mb2[tid];
    __syncthreads();

    int node = blockIdx.x * 256 + tid;
    if (node >= NN) return;

    float h1[32];
#pragma unroll
    for (int j = 0; j < 32; j++) h1[j] = b0s[j];
    const float* xr = g_act + (size_t)node * 64;
#pragma unroll 4
    for (int k = 0; k < 64; k++) {
        float v = lrelu(fmaf(xr[k], g_scale[k], g_shift[k]), 0.01f);
        const float4* wr = (const float4*)(W0s + k * 32);
#pragma unroll
        for (int j = 0; j < 8; j++) {
            float4 w = wr[j];
            h1[4 * j + 0] = fmaf(v, w.x, h1[4 * j + 0]);
            h1[4 * j + 1] = fmaf(v, w.y, h1[4 * j + 1]);
            h1[4 * j + 2] = fmaf(v, w.z, h1[4 * j + 2]);
            h1[4 * j + 3] = fmaf(v, w.w, h1[4 * j + 3]);
        }
    }
    float h2[16];
#pragma unroll
    for (int j = 0; j < 16; j++) h2[j] = b1s[j];
#pragma unroll
    for (int k = 0; k < 32; k++) {
        float v = fmaxf(h1[k], 0.f);
        const float4* wr = (const float4*)(W1s + k * 16);
#pragma unroll
        for (int j = 0; j < 4; j++) {
            float4 w = wr[j];
            h2[4 * j + 0] = fmaf(v, w.x, h2[4 * j + 0]);
            h2[4 * j + 1] = fmaf(v, w.y, h2[4 * j + 1]);
            h2[4 * j + 2] = fmaf(v, w.z, h2[4 * j + 2]);
            h2[4 * j + 3] = fmaf(v, w.w, h2[4 * j + 3]);
        }
    }
    float o0 = b2s[0], o1 = b2s[1];
#pragma unroll
    for (int k = 0; k < 16; k++) {
        float v = fmaxf(h2[k], 0.f);
        o0 = fmaf(v, W2s[k * 2], o0);
        o1 = fmaf(v, W2s[k * 2 + 1], o1);
    }
    *(float2*)(out + (size_t)node * 2) = make_float2(o0, o1);
}

// ----------------------------- driver ----------------------------------------
extern "C" void kernel_launch(void* const* d_in, const int* in_sizes, int n_in,
                              void* d_out, int out_size) {
    const float* x  = (const float*)d_in[0];
    const void*  ei = d_in[1];
    const float* W[3]   = { (const float*)d_in[2],  (const float*)d_in[9],  (const float*)d_in[16] };
    const float* as_[3] = { (const float*)d_in[3],  (const float*)d_in[10], (const float*)d_in[17] };
    const float* ad_[3] = { (const float*)d_in[4],  (const float*)d_in[11], (const float*)d_in[18] };
    const float* b_[3]  = { (const float*)d_in[5],  (const float*)d_in[12], (const float*)d_in[19] };
    const float* gw_[3] = { (const float*)d_in[6],  (const float*)d_in[13], (const float*)d_in[20] };
    const float* gb_[3] = { (const float*)d_in[7],  (const float*)d_in[14], (const float*)d_in[21] };
    const float* ga_[3] = { (const float*)d_in[8],  (const float*)d_in[15], (const float*)d_in[22] };
    const float* mW0 = (const float*)d_in[23]; const float* mb0 = (const float*)d_in[24];
    const float* mW1 = (const float*)d_in[25]; const float* mb1 = (const float*)d_in[26];
    const float* mW2 = (const float*)d_in[27]; const float* mb2 = (const float*)d_in[28];
    float* out = (float*)d_out;

    float* d_h;   cudaGetSymbolAddress((void**)&d_h,   g_h);
    float* d_agg; cudaGetSymbolAddress((void**)&d_agg, g_agg);
    __nv_bfloat16* d_WTh; cudaGetSymbolAddress((void**)&d_WTh, g_WTh);
    __nv_bfloat16* d_WTl; cudaGetSymbolAddress((void**)&d_WTl, g_WTl);

    k_detect<<<1, 1>>>(ei);
    k_zcnt<<<(NN + 255) / 256, 256>>>();
    k_convhist<<<(2 * EE + 255) / 256, 256>>>(ei);
    k_scan1<<<NSCB, 256>>>();
    k_scan2<<<1, 256>>>();
    k_scan3<<<(NN + 255) / 256, 256>>>();
    k_scatter<<<(EPN + 255) / 256, 256>>>();

    for (int L = 0; L < 3; L++) k_prep_w<<<256, 256>>>(W[L], L);

    const int GB = (NN + 127) / 128;
    for (int L = 0; L < 3; L++) {
        const float* Asrc = (L == 0) ? x : d_agg;
        if (L == 0)
            k_gemm<false><<<dim3(GB, 4), 256>>>(Asrc, d_WTh + (size_t)L * 65536,
                                                d_WTl + (size_t)L * 65536, as_[L], ad_[L], d_h);
        else
            k_gemm<true><<<dim3(GB, 4), 256>>>(Asrc, d_WTh + (size_t)L * 65536,
                                               d_WTl + (size_t)L * 65536, as_[L], ad_[L], d_h);
        int mode = (L == 2) ? 1 : 0;
        k_gat<<<(NN * 32 + 255) / 256, 256>>>(b_[L], mode);
        k_scale<<<1, (L == 2) ? 64 : 256>>>(ga_[L], gw_[L], gb_[L], b_[L]);
    }

    k_mlp<<<(NN + 255) / 256, 256>>>(mW0, mb0, mW1, mb1, mW2, mb2, out);
}